// round 1
// baseline (speedup 1.0000x reference)
#include <cuda_runtime.h>
#include <math.h>

#define NN 3072
#define HH 256
#define NB 4
#define HD 64
#define NHID (NN*HH)
#define NSPLIT 3
#define ZRANGE (NN/NSPLIT)   // 1024
#define SCALE 0.125f         // HD^-0.5

// ---------------- device scratch (static; no allocations) ----------------
__device__ float g_hn[NHID];                       // layernormed h
__device__ float g_kt[NB*NN*HD];                   // k  transposed per head [b][n][y]
__device__ float g_mut[NB*NN*HD];                  // mu proj [b][n][y]
__device__ float g_lst[NB*NN*HD];                  // ls proj [b][n][y]
__device__ float g_accP[(size_t)NSPLIT*NN*1024];   // partial aggregation [sp][n][b*256+h]
__device__ float g_denP[NSPLIT*NN*4];              // partial denominators [sp][n][b]
__device__ double g_kl;

// ---------------- LayerNorm ----------------
__global__ void __launch_bounds__(256) ln_kernel(const float* __restrict__ h,
                                                 const float* __restrict__ gamma,
                                                 const float* __restrict__ beta) {
    int n = blockIdx.x, t = threadIdx.x;
    float v = h[n*HH + t];
    float s = v, q = v*v;
    #pragma unroll
    for (int o = 16; o; o >>= 1) {
        s += __shfl_down_sync(0xffffffffu, s, o);
        q += __shfl_down_sync(0xffffffffu, q, o);
    }
    __shared__ float ss[8], qs[8];
    __shared__ float s_m, s_r;
    int lane = t & 31, w = t >> 5;
    if (lane == 0) { ss[w] = s; qs[w] = q; }
    __syncthreads();
    if (t == 0) {
        float S = 0.f, Q = 0.f;
        #pragma unroll
        for (int i = 0; i < 8; i++) { S += ss[i]; Q += qs[i]; }
        float m = S * (1.f/256.f);
        float var = Q * (1.f/256.f) - m*m;
        s_m = m; s_r = rsqrtf(var + 1e-5f);
    }
    __syncthreads();
    g_hn[n*HH + t] = (v - s_m) * s_r * gamma[t] + beta[t];
    if (n == 0 && t == 0) g_kl = 0.0;   // reset accumulator every launch/replay
}

// ---------------- 3 projections (k, mu, ls), head-transposed output ----------------
__global__ void __launch_bounds__(256) proj_kernel(
        const float* __restrict__ Wk, const float* __restrict__ bk,
        const float* __restrict__ Wm, const float* __restrict__ bm,
        const float* __restrict__ Wl, const float* __restrict__ bl) {
    int p = blockIdx.y;
    const float* W  = (p == 0) ? Wk : (p == 1) ? Wm : Wl;
    const float* bi = (p == 0) ? bk : (p == 1) ? bm : bl;
    float* dst      = (p == 0) ? g_kt : (p == 1) ? g_mut : g_lst;

    __shared__ float hs[16][HH];
    int t = threadIdx.x;
    int r0 = blockIdx.x * 16;
    for (int idx = t; idx < 16*HH; idx += 256)
        hs[idx >> 8][idx & 255] = g_hn[(r0 + (idx >> 8))*HH + (idx & 255)];
    __syncthreads();

    float acc[16];
    #pragma unroll
    for (int r = 0; r < 16; r++) acc[r] = 0.f;

    for (int k = 0; k < HH; k += 4) {
        float w0 = W[(k+0)*HH + t];
        float w1 = W[(k+1)*HH + t];
        float w2 = W[(k+2)*HH + t];
        float w3 = W[(k+3)*HH + t];
        #pragma unroll
        for (int r = 0; r < 16; r++) {
            float4 hv = *(const float4*)&hs[r][k];
            acc[r] += hv.x*w0 + hv.y*w1 + hv.z*w2 + hv.w*w3;
        }
    }
    float bb = bi[t];
    int y = t >> 2, b = t & 3;                 // reshape(N, HD, B): col = y*B + b
    #pragma unroll
    for (int r = 0; r < 16; r++)
        dst[((size_t)b*NN + r0 + r)*HD + y] = acc[r] + bb;
}

// ---------------- fused attention / KL / aggregation ----------------
// grid: 96 x-tiles * NSPLIT z-splits = 288 CTAs, 512 threads
// smem floats: k_s 8192 | mu_s 4*32*76 | ls_s 4*32*76 | hn_s 8192 | a_s 4096
#define SMEM_FLOATS (8192 + 9728 + 9728 + 8192 + 4096)

__device__ __forceinline__ float4 f4fma(float s, float4 v, float4 a) {
    a.x += s*v.x; a.y += s*v.y; a.z += s*v.z; a.w += s*v.w; return a;
}

__global__ void __launch_bounds__(512, 1) attn_kernel(const float* __restrict__ diffusion,
                                                      const float* __restrict__ eps) {
    extern __shared__ float smem[];
    float* k_s  = smem;               // [b][32][64]
    float* mu_s = k_s  + 8192;        // [b][32][76]  (pad 76 -> conflict-free)
    float* ls_s = mu_s + 9728;
    float* hn_s = ls_s + 9728;        // [32][256]
    float* a_s  = hn_s + 8192;        // [32 x][32 z][4 b]
    __shared__ float red[16];

    int tid  = threadIdx.x;
    int xt   = blockIdx.x / NSPLIT;
    int sp   = blockIdx.x % NSPLIT;
    int x0   = xt * 32;
    int z0   = sp * ZRANGE;
    int lane = tid & 31, warp = tid >> 5;   // score phase: x = warp / warp+16, z = lane
    int xa   = tid >> 4,  j   = tid & 15;   // agg phase: thread covers f4 cols {j,j+16,j+32,j+48}

    // load k tile once
    for (int idx = tid; idx < 8192; idx += 512) {
        int b = idx >> 11, x = (idx >> 6) & 31, y = idx & 63;
        k_s[idx] = g_kt[((size_t)b*NN + x0 + x)*HD + y];
    }

    float4 acc[4][4];
    #pragma unroll
    for (int b = 0; b < 4; b++)
        #pragma unroll
        for (int c = 0; c < 4; c++) acc[b][c] = make_float4(0.f,0.f,0.f,0.f);
    float4 den = make_float4(0.f,0.f,0.f,0.f);
    float klloc = 0.f;

    const float4* k4 = (const float4*)k_s;
    const float4* m4 = (const float4*)mu_s;
    const float4* l4 = (const float4*)ls_s;
    const float4* h4 = (const float4*)hn_s;
    const float4* e4 = (const float4*)eps;

    for (int it = 0; it < ZRANGE/32; ++it) {
        int zb = z0 + it*32;
        __syncthreads();
        // stage mu/ls (padded rows) and hn
        {
            int row = tid >> 2;                 // 0..127 -> (b,z)
            int b = row >> 5, z = row & 31;
            int c0 = (tid & 3) * 16;
            const float* sm = &g_mut[((size_t)b*NN + zb + z)*HD + c0];
            const float* sl = &g_lst[((size_t)b*NN + zb + z)*HD + c0];
            float* dm = &mu_s[(b*32 + z)*76 + c0];
            float* dl = &ls_s[(b*32 + z)*76 + c0];
            #pragma unroll
            for (int i = 0; i < 4; i++) {
                *(float4*)(dm + 4*i) = *(const float4*)(sm + 4*i);
                *(float4*)(dl + 4*i) = *(const float4*)(sl + 4*i);
            }
            int zr = tid >> 4, h0 = (tid & 15) * 16;
            const float* sh = &g_hn[(size_t)(zb + zr)*HH + h0];
            float* dh = &hn_s[zr*HH + h0];
            #pragma unroll
            for (int i = 0; i < 4; i++)
                *(float4*)(dh + 4*i) = *(const float4*)(sh + 4*i);
        }
        __syncthreads();

        // ---- scores: two x rows (warp, warp+16) vs z=lane, all 4 heads ----
        float mu0[4], ls0[4], mu1[4], ls1[4];
        #pragma unroll
        for (int b = 0; b < 4; b++) {
            const float4* kp0 = k4 + (b*32 + warp)      * 16;
            const float4* kp1 = k4 + (b*32 + warp + 16) * 16;
            const float4* mp  = m4 + (b*32 + lane) * 19;
            const float4* lp  = l4 + (b*32 + lane) * 19;
            float am0 = 0.f, al0 = 0.f, am1 = 0.f, al1 = 0.f;
            #pragma unroll
            for (int y = 0; y < 16; y++) {
                float4 kv0 = kp0[y], kv1 = kp1[y], mv = mp[y], lv = lp[y];
                am0 += kv0.x*mv.x + kv0.y*mv.y + kv0.z*mv.z + kv0.w*mv.w;
                al0 += kv0.x*lv.x + kv0.y*lv.y + kv0.z*lv.z + kv0.w*lv.w;
                am1 += kv1.x*mv.x + kv1.y*mv.y + kv1.z*mv.z + kv1.w*mv.w;
                al1 += kv1.x*lv.x + kv1.y*lv.y + kv1.z*lv.z + kv1.w*lv.w;
            }
            mu0[b] = SCALE*am0; ls0[b] = SCALE*al0;
            mu1[b] = SCALE*am1; ls1[b] = SCALE*al1;
        }

        // ---- elementwise: sigma, kl, a ----
        #pragma unroll
        for (int pp = 0; pp < 2; pp++) {
            int xs = warp + 16*pp;
            float* mu = pp ? mu1 : mu0;
            float* ls = pp ? ls1 : ls0;
            size_t g = (size_t)(x0 + xs)*NN + (size_t)(zb + lane);
            float d  = diffusion[g];
            float4 e = e4[g];
            float ec[4] = {e.x, e.y, e.z, e.w};
            float sg = (d > 0.f) ? 1.f : ((d < 0.f) ? -1.f : 0.f);
            float klp = 0.f;
            float av[4];
            #pragma unroll
            for (int b = 0; b < 4; b++) {
                float sig = __logf(1.f + __expf(ls[b]));          // softplus
                av[b] = __expf(mu[b] + sig*ec[b]) * d;
                klp  += 0.5f*(sig*sig + mu[b]*mu[b]) - 0.5f - __logf(sig);
            }
            klloc += sg * klp;
            ((float4*)a_s)[xs*32 + lane] = make_float4(av[0], av[1], av[2], av[3]);
        }
        __syncthreads();

        // ---- aggregation: acc[x][b][:] += a[x][z][b] * hn[z][:] ----
        const float4* as4 = ((const float4*)a_s) + xa*32;
        #pragma unroll 2
        for (int z = 0; z < 32; z++) {
            float4 a4 = as4[z];
            den.x += a4.x; den.y += a4.y; den.z += a4.z; den.w += a4.w;
            const float4* hr = h4 + z*64 + j;
            #pragma unroll
            for (int c = 0; c < 4; c++) {
                float4 hv = hr[16*c];
                acc[0][c] = f4fma(a4.x, hv, acc[0][c]);
                acc[1][c] = f4fma(a4.y, hv, acc[1][c]);
                acc[2][c] = f4fma(a4.z, hv, acc[2][c]);
                acc[3][c] = f4fma(a4.w, hv, acc[3][c]);
            }
        }
    }

    // ---- writeback partials ----
    {
        int n = x0 + xa;
        float* ap = g_accP + ((size_t)sp*NN + n)*1024;
        #pragma unroll
        for (int b = 0; b < 4; b++)
            #pragma unroll
            for (int c = 0; c < 4; c++)
                *(float4*)(ap + b*256 + c*64 + j*4) = acc[b][c];
        if (j == 0)
            *(float4*)(g_denP + ((size_t)sp*NN + n)*4) = den;
    }
    // ---- kl reduce ----
    #pragma unroll
    for (int o = 16; o; o >>= 1) klloc += __shfl_down_sync(0xffffffffu, klloc, o);
    if (lane == 0) red[warp] = klloc;
    __syncthreads();
    if (tid == 0) {
        float s = 0.f;
        #pragma unroll
        for (int i = 0; i < 16; i++) s += red[i];
        atomicAdd(&g_kl, (double)s);
    }
}

// ---------------- normalize + fc_v + elu + residual + kl tail ----------------
__global__ void __launch_bounds__(256) final_kernel(const float* __restrict__ Wv,
                                                    const float* __restrict__ bv,
                                                    const float* __restrict__ h0,
                                                    float* __restrict__ out,
                                                    int out_size) {
    __shared__ float vs[8][1024];
    int t = threadIdx.x;
    int r0 = blockIdx.x * 8;

    for (int idx = t; idx < 8*256; idx += 256) {   // f4 granularity
        int r = idx >> 8, c4 = idx & 255;
        int n = r0 + r;
        float4 a0 = *((const float4*)(g_accP + ((size_t)0*NN + n)*1024) + c4);
        float4 a1 = *((const float4*)(g_accP + ((size_t)1*NN + n)*1024) + c4);
        float4 a2 = *((const float4*)(g_accP + ((size_t)2*NN + n)*1024) + c4);
        int b = c4 >> 6;
        float dsum = g_denP[((size_t)0*NN + n)*4 + b]
                   + g_denP[((size_t)1*NN + n)*4 + b]
                   + g_denP[((size_t)2*NN + n)*4 + b];
        float inv = 1.f / fmaxf(dsum, 1e-12f);
        float4 s;
        s.x = (a0.x + a1.x + a2.x) * inv;
        s.y = (a0.y + a1.y + a2.y) * inv;
        s.z = (a0.z + a1.z + a2.z) * inv;
        s.w = (a0.w + a1.w + a2.w) * inv;
        *(float4*)&vs[r][c4*4] = s;
    }
    __syncthreads();

    float o[8];
    #pragma unroll
    for (int r = 0; r < 8; r++) o[r] = 0.f;
    for (int k = 0; k < 1024; k += 4) {
        float w0 = Wv[(size_t)(k+0)*HH + t];
        float w1 = Wv[(size_t)(k+1)*HH + t];
        float w2 = Wv[(size_t)(k+2)*HH + t];
        float w3 = Wv[(size_t)(k+3)*HH + t];
        #pragma unroll
        for (int r = 0; r < 8; r++) {
            float4 hv = *(const float4*)&vs[r][k];
            o[r] += hv.x*w0 + hv.y*w1 + hv.z*w2 + hv.w*w3;
        }
    }
    float bb = bv[t];
    #pragma unroll
    for (int r = 0; r < 8; r++) {
        float u = o[r] + bb;
        u = (u > 0.f) ? u : expm1f(u);          // elu
        out[(size_t)(r0 + r)*HH + t] = u + h0[(size_t)(r0 + r)*HH + t];
    }
    if (blockIdx.x == 0 && t == 0) {
        float klv = (float)(g_kl / ((double)NN * (double)NN));
        for (int i = NHID; i < out_size; i++) out[i] = klv;
    }
}

// ---------------- launch ----------------
extern "C" void kernel_launch(void* const* d_in, const int* in_sizes, int n_in,
                              void* d_out, int out_size) {
    const float* h     = (const float*)d_in[0];
    const float* gamma = (const float*)d_in[1];
    const float* beta  = (const float*)d_in[2];
    const float* Wk    = (const float*)d_in[3];
    const float* bk    = (const float*)d_in[4];
    const float* Wm    = (const float*)d_in[5];
    const float* bm    = (const float*)d_in[6];
    const float* Wl    = (const float*)d_in[7];
    const float* bl    = (const float*)d_in[8];
    const float* Wv    = (const float*)d_in[9];
    const float* bv    = (const float*)d_in[10];
    const float* diff  = (const float*)d_in[11];
    const float* eps   = (const float*)d_in[12];
    float* out = (float*)d_out;

    cudaFuncSetAttribute(attn_kernel, cudaFuncAttributeMaxDynamicSharedMemorySize,
                         SMEM_FLOATS * (int)sizeof(float));

    ln_kernel<<<NN, 256>>>(h, gamma, beta);
    dim3 gp(NN/16, 3);
    proj_kernel<<<gp, 256>>>(Wk, bk, Wm, bm, Wl, bl);
    attn_kernel<<<96*NSPLIT, 512, SMEM_FLOATS * (int)sizeof(float)>>>(diff, eps);
    final_kernel<<<NN/8, 256>>>(Wv, bv, h, out, out_size);
}

// round 2
// speedup vs baseline: 2.2452x; 2.2452x over previous
#include <cuda_runtime.h>
#include <cuda_bf16.h>
#include <stdint.h>
#include <math.h>

#define NN 3072
#define HH 256
#define HD 64
#define NHID (NN*HH)
#define NSPLIT 3
#define ZRANGE (NN/NSPLIT)   // 1024
#define SCALE 0.125f         // HD^-0.5

// ---------------- device scratch (static; no allocations) ----------------
__device__ float g_hn[NHID];                          // layernormed h (fp32, proj input)
__device__ __nv_bfloat16 g_hnT[HH*NN];                // hn transposed [h][n] bf16 (agg B operand)
__device__ __nv_bfloat16 g_kt[4*NN*HD];               // k  per head [b][n][y] bf16
__device__ __nv_bfloat16 g_mut[4*NN*HD];              // mu per head bf16
__device__ __nv_bfloat16 g_lst[4*NN*HD];              // ls per head bf16
__device__ float g_accP[(size_t)NSPLIT*NN*1024];      // partial agg [sp][n][b*256+h]
__device__ float g_denP[NSPLIT*NN*4];                 // partial denominators [sp][n][b]
__device__ double g_kl;

// ---------------- bf16 mma.sync m16n8k16 helper ----------------
__device__ __forceinline__ void mma16816(float d[4], const uint32_t a[4],
                                         uint32_t b0, uint32_t b1) {
    asm volatile(
        "mma.sync.aligned.m16n8k16.row.col.f32.bf16.bf16.f32 "
        "{%0,%1,%2,%3},{%4,%5,%6,%7},{%8,%9},{%0,%1,%2,%3};\n"
        : "+f"(d[0]), "+f"(d[1]), "+f"(d[2]), "+f"(d[3])
        : "r"(a[0]), "r"(a[1]), "r"(a[2]), "r"(a[3]), "r"(b0), "r"(b1));
}

// ---------------- LayerNorm (+ bf16 transposed copy) ----------------
__global__ void __launch_bounds__(256) ln_kernel(const float* __restrict__ h,
                                                 const float* __restrict__ gamma,
                                                 const float* __restrict__ beta) {
    int n = blockIdx.x, t = threadIdx.x;
    float v = h[n*HH + t];
    float s = v, q = v*v;
    #pragma unroll
    for (int o = 16; o; o >>= 1) {
        s += __shfl_down_sync(0xffffffffu, s, o);
        q += __shfl_down_sync(0xffffffffu, q, o);
    }
    __shared__ float ss[8], qs[8];
    __shared__ float s_m, s_r;
    int lane = t & 31, w = t >> 5;
    if (lane == 0) { ss[w] = s; qs[w] = q; }
    __syncthreads();
    if (t == 0) {
        float S = 0.f, Q = 0.f;
        #pragma unroll
        for (int i = 0; i < 8; i++) { S += ss[i]; Q += qs[i]; }
        float m = S * (1.f/256.f);
        float var = Q * (1.f/256.f) - m*m;
        s_m = m; s_r = rsqrtf(var + 1e-5f);
    }
    __syncthreads();
    float hn = (v - s_m) * s_r * gamma[t] + beta[t];
    g_hn[n*HH + t] = hn;
    g_hnT[(size_t)t*NN + n] = __float2bfloat16(hn);
    if (n == 0 && t == 0) g_kl = 0.0;
}

// ---------------- 3 projections (k, mu, ls) -> bf16 head-transposed ----------------
__global__ void __launch_bounds__(256) proj_kernel(
        const float* __restrict__ Wk, const float* __restrict__ bk,
        const float* __restrict__ Wm, const float* __restrict__ bm,
        const float* __restrict__ Wl, const float* __restrict__ bl) {
    int p = blockIdx.y;
    const float* W  = (p == 0) ? Wk : (p == 1) ? Wm : Wl;
    const float* bi = (p == 0) ? bk : (p == 1) ? bm : bl;
    __nv_bfloat16* dst = (p == 0) ? g_kt : (p == 1) ? g_mut : g_lst;

    __shared__ float hs[16][HH];
    int t = threadIdx.x;
    int r0 = blockIdx.x * 16;
    for (int idx = t; idx < 16*HH; idx += 256)
        hs[idx >> 8][idx & 255] = g_hn[(r0 + (idx >> 8))*HH + (idx & 255)];
    __syncthreads();

    float acc[16];
    #pragma unroll
    for (int r = 0; r < 16; r++) acc[r] = 0.f;

    for (int k = 0; k < HH; k += 4) {
        float w0 = W[(k+0)*HH + t];
        float w1 = W[(k+1)*HH + t];
        float w2 = W[(k+2)*HH + t];
        float w3 = W[(k+3)*HH + t];
        #pragma unroll
        for (int r = 0; r < 16; r++) {
            float4 hv = *(const float4*)&hs[r][k];
            acc[r] += hv.x*w0 + hv.y*w1 + hv.z*w2 + hv.w*w3;
        }
    }
    float bb = bi[t];
    int y = t >> 2, b = t & 3;                 // reshape(N, HD, B): col = y*B + b
    #pragma unroll
    for (int r = 0; r < 16; r++)
        dst[((size_t)b*NN + r0 + r)*HD + y] = __float2bfloat16(acc[r] + bb);
}

// ---------------- fused attention / KL / aggregation (bf16 HMMA) ----------------
// smem (bf16 elems): k_s 4*32*72 | mu_s 4*64*72 | ls_s 4*64*72 | hn_s 256*72
#define K_S_ELEMS  (4*32*72)
#define MU_S_ELEMS (4*64*72)
#define HN_S_ELEMS (256*72)
#define ATTN_SMEM_BYTES ((K_S_ELEMS + 2*MU_S_ELEMS + HN_S_ELEMS) * 2)

__global__ void __launch_bounds__(256, 1) attn_kernel(const float* __restrict__ diff,
                                                      const float* __restrict__ eps) {
    extern __shared__ __nv_bfloat16 smb[];
    __nv_bfloat16* k_s  = smb;                        // [4][32][72]
    __nv_bfloat16* mu_s = k_s + K_S_ELEMS;            // [4][64][72]
    __nv_bfloat16* ls_s = mu_s + MU_S_ELEMS;          // [4][64][72]
    __nv_bfloat16* hn_s = ls_s + MU_S_ELEMS;          // [256][72]  (hnT tile: [h][z])
    __shared__ float red[8];

    const int tid = threadIdx.x;
    const int xt = blockIdx.x / NSPLIT, sp = blockIdx.x % NSPLIT;
    const int x0 = xt * 32, zbase = sp * ZRANGE;
    const int w = tid >> 5, l = tid & 31;
    const int b = w >> 1, xh = w & 1;       // head, x-half (m16)
    const int g = l >> 2, t2 = (l & 3) * 2; // mma fragment coords

    // stage K tile once: 128 rows (b,x) of 64 bf16
    {
        int row = tid >> 1, half = tid & 1;
        int br = row >> 5, xr = row & 31;
        const uint4* src = (const uint4*)(g_kt + ((size_t)br*NN + x0 + xr)*HD + half*32);
        uint4* dst = (uint4*)(k_s + (br*32 + xr)*72 + half*32);
        dst[0] = src[0]; dst[1] = src[1]; dst[2] = src[2]; dst[3] = src[3];
    }

    float acc[32][4];
    #pragma unroll
    for (int nt = 0; nt < 32; nt++) { acc[nt][0]=0.f; acc[nt][1]=0.f; acc[nt][2]=0.f; acc[nt][3]=0.f; }
    float den0 = 0.f, den1 = 0.f, klloc = 0.f;
    uint32_t kfr[4][4];

    const int xr_lo = x0 + xh*16 + g;

    for (int zi = 0; zi < ZRANGE/64; ++zi) {
        const int zb = zbase + zi*64;
        __syncthreads();
        {   // stage mu/ls tiles [4][64][64] and hnT tile [256][64]
            const uint4* sm_ = (const uint4*)(g_mut + ((size_t)(tid>>6)*NN + zb + (tid&63))*HD);
            const uint4* sl_ = (const uint4*)(g_lst + ((size_t)(tid>>6)*NN + zb + (tid&63))*HD);
            uint4* dm_ = (uint4*)(mu_s + tid*72);
            uint4* dl_ = (uint4*)(ls_s + tid*72);
            #pragma unroll
            for (int i = 0; i < 8; i++) { dm_[i] = sm_[i]; dl_[i] = sl_[i]; }
            const uint4* sh_ = (const uint4*)(g_hnT + (size_t)tid*NN + zb);
            uint4* dh_ = (uint4*)(hn_s + tid*72);
            #pragma unroll
            for (int i = 0; i < 8; i++) dh_[i] = sh_[i];
        }
        __syncthreads();

        if (zi == 0) {   // load K A-fragments (after k_s visible)
            #pragma unroll
            for (int kt = 0; kt < 4; kt++) {
                const __nv_bfloat16* base = k_s + (b*32 + xh*16)*72 + kt*16;
                kfr[kt][0] = *(const uint32_t*)(base + (size_t)g*72     + t2);
                kfr[kt][1] = *(const uint32_t*)(base + (size_t)(g+8)*72 + t2);
                kfr[kt][2] = *(const uint32_t*)(base + (size_t)g*72     + t2 + 8);
                kfr[kt][3] = *(const uint32_t*)(base + (size_t)(g+8)*72 + t2 + 8);
            }
        }

        #pragma unroll
        for (int zk = 0; zk < 4; zk++) {
            // ---- prefetch diffusion / eps for this 16x x 16z block ----
            float2 dif[2][2]; float ep[2][2][2];
            #pragma unroll
            for (int t = 0; t < 2; t++)
                #pragma unroll
                for (int rr = 0; rr < 2; rr++) {
                    int xg = xr_lo + rr*8;
                    int zg = zb + zk*16 + t*8 + t2;
                    size_t gidx = (size_t)xg*NN + zg;
                    dif[t][rr] = *(const float2*)(diff + gidx);
                    ep[t][rr][0] = eps[gidx*4 + b];
                    ep[t][rr][1] = eps[(gidx+1)*4 + b];
                }

            // ---- score MMAs: S_mu, S_ls [16x, 16z] for this head ----
            float dmu[2][4], dls[2][4];
            #pragma unroll
            for (int t = 0; t < 2; t++) {
                dmu[t][0]=0.f; dmu[t][1]=0.f; dmu[t][2]=0.f; dmu[t][3]=0.f;
                dls[t][0]=0.f; dls[t][1]=0.f; dls[t][2]=0.f; dls[t][3]=0.f;
            }
            #pragma unroll
            for (int kt = 0; kt < 4; kt++) {
                #pragma unroll
                for (int t = 0; t < 2; t++) {
                    int zr = zk*16 + t*8 + g;
                    const __nv_bfloat16* mrow = mu_s + ((size_t)(b*64 + zr))*72 + kt*16 + t2;
                    const __nv_bfloat16* lrow = ls_s + ((size_t)(b*64 + zr))*72 + kt*16 + t2;
                    uint32_t mb0 = *(const uint32_t*)mrow;
                    uint32_t mb1 = *(const uint32_t*)(mrow + 8);
                    mma16816(dmu[t], kfr[kt], mb0, mb1);
                    uint32_t lb0 = *(const uint32_t*)lrow;
                    uint32_t lb1 = *(const uint32_t*)(lrow + 8);
                    mma16816(dls[t], kfr[kt], lb0, lb1);
                }
            }

            // ---- elementwise: softplus, sample, KL; pack a into A-fragment ----
            uint32_t af[4];
            #pragma unroll
            for (int t = 0; t < 2; t++) {
                #pragma unroll
                for (int rr = 0; rr < 2; rr++) {
                    float m0 = dmu[t][rr*2]   * SCALE;
                    float m1 = dmu[t][rr*2+1] * SCALE;
                    float s0 = dls[t][rr*2]   * SCALE;
                    float s1 = dls[t][rr*2+1] * SCALE;
                    float sg0 = __logf(1.f + __expf(s0));
                    float sg1 = __logf(1.f + __expf(s1));
                    float d0 = dif[t][rr].x, d1 = dif[t][rr].y;
                    float a0 = __expf(fmaf(sg0, ep[t][rr][0], m0)) * d0;
                    float a1 = __expf(fmaf(sg1, ep[t][rr][1], m1)) * d1;
                    float sn0 = (d0 > 0.f) ? 1.f : ((d0 < 0.f) ? -1.f : 0.f);
                    float sn1 = (d1 > 0.f) ? 1.f : ((d1 < 0.f) ? -1.f : 0.f);
                    klloc += sn0 * (0.5f*(sg0*sg0 + m0*m0) - 0.5f - __logf(sg0));
                    klloc += sn1 * (0.5f*(sg1*sg1 + m1*m1) - 0.5f - __logf(sg1));
                    if (rr == 0) den0 += a0 + a1; else den1 += a0 + a1;
                    __nv_bfloat162 p = __float22bfloat162_rn(make_float2(a0, a1));
                    af[t*2 + rr] = *(uint32_t*)&p;
                }
            }

            // ---- aggregation MMAs: acc[16x, 256h] += a[16x,16z] @ hn[16z,256h] ----
            #pragma unroll
            for (int nt = 0; nt < 32; nt++) {
                const __nv_bfloat16* hrow = hn_s + ((size_t)(nt*8 + g))*72 + zk*16 + t2;
                uint32_t hb0 = *(const uint32_t*)hrow;
                uint32_t hb1 = *(const uint32_t*)(hrow + 8);
                mma16816(acc[nt], af, hb0, hb1);
            }
        }
    }

    // ---- epilogue: write partial acc + denominators ----
    {
        float* outlo = g_accP + ((size_t)sp*NN + xr_lo)*1024 + b*256;
        float* outhi = outlo + (size_t)8*1024;
        #pragma unroll
        for (int nt = 0; nt < 32; nt++) {
            *(float2*)(outlo + nt*8 + t2) = make_float2(acc[nt][0], acc[nt][1]);
            *(float2*)(outhi + nt*8 + t2) = make_float2(acc[nt][2], acc[nt][3]);
        }
        den0 += __shfl_xor_sync(0xffffffffu, den0, 1);
        den0 += __shfl_xor_sync(0xffffffffu, den0, 2);
        den1 += __shfl_xor_sync(0xffffffffu, den1, 1);
        den1 += __shfl_xor_sync(0xffffffffu, den1, 2);
        if ((l & 3) == 0) {
            g_denP[((size_t)sp*NN + xr_lo)*4 + b]     = den0;
            g_denP[((size_t)sp*NN + xr_lo + 8)*4 + b] = den1;
        }
    }
    // ---- kl reduce ----
    #pragma unroll
    for (int o = 16; o; o >>= 1) klloc += __shfl_down_sync(0xffffffffu, klloc, o);
    if (l == 0) red[w] = klloc;
    __syncthreads();
    if (tid == 0) {
        float s = 0.f;
        #pragma unroll
        for (int i = 0; i < 8; i++) s += red[i];
        atomicAdd(&g_kl, (double)s);
    }
}

// ---------------- normalize + fc_v + elu + residual + kl tail ----------------
__global__ void __launch_bounds__(256) final_kernel(const float* __restrict__ Wv,
                                                    const float* __restrict__ bv,
                                                    const float* __restrict__ h0,
                                                    float* __restrict__ out,
                                                    int out_size) {
    extern __shared__ float vs[];   // [16][1024]
    int t = threadIdx.x;
    int r0 = blockIdx.x * 16;

    for (int idx = t; idx < 16*256; idx += 256) {
        int r = idx >> 8, c4 = idx & 255;
        int n = r0 + r;
        float4 a0 = *((const float4*)(g_accP + ((size_t)0*NN + n)*1024) + c4);
        float4 a1 = *((const float4*)(g_accP + ((size_t)1*NN + n)*1024) + c4);
        float4 a2 = *((const float4*)(g_accP + ((size_t)2*NN + n)*1024) + c4);
        int b = c4 >> 6;
        float dsum = g_denP[((size_t)0*NN + n)*4 + b]
                   + g_denP[((size_t)1*NN + n)*4 + b]
                   + g_denP[((size_t)2*NN + n)*4 + b];
        float inv = 1.f / fmaxf(dsum, 1e-12f);
        float4 s;
        s.x = (a0.x + a1.x + a2.x) * inv;
        s.y = (a0.y + a1.y + a2.y) * inv;
        s.z = (a0.z + a1.z + a2.z) * inv;
        s.w = (a0.w + a1.w + a2.w) * inv;
        *(float4*)&vs[r*1024 + c4*4] = s;
    }
    __syncthreads();

    float o[16];
    #pragma unroll
    for (int r = 0; r < 16; r++) o[r] = 0.f;
    for (int k = 0; k < 1024; k += 4) {
        float w0 = Wv[(size_t)(k+0)*HH + t];
        float w1 = Wv[(size_t)(k+1)*HH + t];
        float w2 = Wv[(size_t)(k+2)*HH + t];
        float w3 = Wv[(size_t)(k+3)*HH + t];
        #pragma unroll
        for (int r = 0; r < 16; r++) {
            float4 hv = *(const float4*)&vs[r*1024 + k];
            o[r] += hv.x*w0 + hv.y*w1 + hv.z*w2 + hv.w*w3;
        }
    }
    float bb = bv[t];
    #pragma unroll
    for (int r = 0; r < 16; r++) {
        float u = o[r] + bb;
        u = (u > 0.f) ? u : expm1f(u);
        out[(size_t)(r0 + r)*HH + t] = u + h0[(size_t)(r0 + r)*HH + t];
    }
    if (blockIdx.x == 0 && t == 0) {
        float klv = (float)(g_kl / ((double)NN * (double)NN));
        for (int i = NHID; i < out_size; i++) out[i] = klv;
    }
}

// ---------------- launch ----------------
extern "C" void kernel_launch(void* const* d_in, const int* in_sizes, int n_in,
                              void* d_out, int out_size) {
    const float* h     = (const float*)d_in[0];
    const float* gamma = (const float*)d_in[1];
    const float* beta  = (const float*)d_in[2];
    const float* Wk    = (const float*)d_in[3];
    const float* bk    = (const float*)d_in[4];
    const float* Wm    = (const float*)d_in[5];
    const float* bm    = (const float*)d_in[6];
    const float* Wl    = (const float*)d_in[7];
    const float* bl    = (const float*)d_in[8];
    const float* Wv    = (const float*)d_in[9];
    const float* bv    = (const float*)d_in[10];
    const float* diff  = (const float*)d_in[11];
    const float* eps   = (const float*)d_in[12];
    float* out = (float*)d_out;

    cudaFuncSetAttribute(attn_kernel, cudaFuncAttributeMaxDynamicSharedMemorySize,
                         ATTN_SMEM_BYTES);
    cudaFuncSetAttribute(final_kernel, cudaFuncAttributeMaxDynamicSharedMemorySize,
                         16*1024*(int)sizeof(float));

    ln_kernel<<<NN, 256>>>(h, gamma, beta);
    dim3 gp(NN/16, 3);
    proj_kernel<<<gp, 256>>>(Wk, bk, Wm, bm, Wl, bl);
    attn_kernel<<<(NN/32)*NSPLIT, 256, ATTN_SMEM_BYTES>>>(diff, eps);
    final_kernel<<<NN/16, 256, 16*1024*sizeof(float)>>>(Wv, bv, h, out, out_size);
}

// round 4
// speedup vs baseline: 3.8137x; 1.6986x over previous
#include <cuda_runtime.h>
#include <cuda_bf16.h>
#include <stdint.h>
#include <math.h>

#define NN 3072
#define HH 256
#define HD 64
#define NHID (NN*HH)
#define NSPLIT 3
#define ZRANGE (NN/NSPLIT)   // 1024
#define SCALE 0.125f         // HD^-0.5

// ---------------- device scratch (static; no allocations) ----------------
__device__ __nv_bfloat16 g_hnB[NHID];                 // hn row-major bf16 (proj A)
__device__ __nv_bfloat16 g_hnT[HH*NN];                // hn transposed [h][n] bf16
__device__ __nv_bfloat16 g_kt[4*NN*HD];               // k  per head [b][n][y]
__device__ __nv_bfloat16 g_mut[4*NN*HD];              // mu per head
__device__ __nv_bfloat16 g_lst[4*NN*HD];              // ls per head
__device__ __nv_bfloat16 g_WT[3*HH*HH];               // W_{k,mu,ls}^T bf16 [o][k]
__device__ __nv_bfloat16 g_WvT[HH*4*HH];              // W_v^T bf16 [256 o][1024 k]
__device__ float g_accP[(size_t)NSPLIT*NN*1024];      // partial agg [sp][n][b*256+h]
__device__ float g_denP[NSPLIT*NN*4];                 // partial denominators
__device__ double g_kl;

// ---------------- bf16 mma.sync m16n8k16 ----------------
__device__ __forceinline__ void mma16816(float d[4], const uint32_t a[4],
                                         uint32_t b0, uint32_t b1) {
    asm volatile(
        "mma.sync.aligned.m16n8k16.row.col.f32.bf16.bf16.f32 "
        "{%0,%1,%2,%3},{%4,%5,%6,%7},{%8,%9},{%0,%1,%2,%3};\n"
        : "+f"(d[0]), "+f"(d[1]), "+f"(d[2]), "+f"(d[3])
        : "r"(a[0]), "r"(a[1]), "r"(a[2]), "r"(a[3]), "r"(b0), "r"(b1));
}

// ---------------- LayerNorm -> bf16 row + transposed copies ----------------
__global__ void __launch_bounds__(256) ln_kernel(const float* __restrict__ h,
                                                 const float* __restrict__ gamma,
                                                 const float* __restrict__ beta) {
    int n = blockIdx.x, t = threadIdx.x;
    float v = h[n*HH + t];
    float s = v, q = v*v;
    #pragma unroll
    for (int o = 16; o; o >>= 1) {
        s += __shfl_down_sync(0xffffffffu, s, o);
        q += __shfl_down_sync(0xffffffffu, q, o);
    }
    __shared__ float ss[8], qs[8];
    __shared__ float s_m, s_r;
    int lane = t & 31, w = t >> 5;
    if (lane == 0) { ss[w] = s; qs[w] = q; }
    __syncthreads();
    if (t == 0) {
        float S = 0.f, Q = 0.f;
        #pragma unroll
        for (int i = 0; i < 8; i++) { S += ss[i]; Q += qs[i]; }
        float m = S * (1.f/256.f);
        float var = Q * (1.f/256.f) - m*m;
        s_m = m; s_r = rsqrtf(var + 1e-5f);
    }
    __syncthreads();
    float hn = (v - s_m) * s_r * gamma[t] + beta[t];
    __nv_bfloat16 hb = __float2bfloat16(hn);
    g_hnB[(size_t)n*HH + t] = hb;
    g_hnT[(size_t)t*NN + n] = hb;
    if (n == 0 && t == 0) g_kl = 0.0;
}

// ---------------- transpose-convert: src fp32 [K][O] -> dst bf16 [O][K] ----------------
__global__ void __launch_bounds__(256) trans_kernel(const float* __restrict__ src,
                                                    __nv_bfloat16* __restrict__ dst,
                                                    int K, int O) {
    __shared__ float s[32][33];
    int tx = threadIdx.x & 31, ty = threadIdx.x >> 5;
    int o0 = blockIdx.x*32, k0 = blockIdx.y*32;
    #pragma unroll
    for (int j = 0; j < 32; j += 8)
        s[ty+j][tx] = src[(size_t)(k0+ty+j)*O + o0+tx];
    __syncthreads();
    #pragma unroll
    for (int j = 0; j < 32; j += 8)
        dst[(size_t)(o0+ty+j)*K + k0+tx] = __float2bfloat16(s[tx][ty+j]);
}

// ---------------- 3 projections (bf16 HMMA) -> head-transposed bf16 ----------------
#define PROJ_SMEM ((64*264 + 256*72)*2)
__global__ void __launch_bounds__(256) proj_kernel(const float* __restrict__ bk,
                                                   const float* __restrict__ bm,
                                                   const float* __restrict__ bl) {
    extern __shared__ __nv_bfloat16 ps[];
    __nv_bfloat16* a_s = ps;            // [64][264]
    __nv_bfloat16* b_s = ps + 64*264;   // [256][72]
    int p = blockIdx.y;
    const __nv_bfloat16* WT = g_WT + (size_t)p*HH*HH;
    const float* bi = (p == 0) ? bk : (p == 1) ? bm : bl;
    __nv_bfloat16* dst = (p == 0) ? g_kt : (p == 1) ? g_mut : g_lst;
    int tid = threadIdx.x;
    int r0 = blockIdx.x * 64;

    #pragma unroll
    for (int j = 0; j < 8; j++) {
        int idx = j*256 + tid; int row = idx >> 5, u = idx & 31;
        *(uint4*)(a_s + row*264 + u*8) =
            *(const uint4*)(g_hnB + (size_t)(r0+row)*HH + u*8);
    }

    int w = tid >> 5, l = tid & 31, g = l >> 2, t2 = (l & 3)*2;
    int wm = w >> 1, wn = w & 1;
    float acc[16][4];
    #pragma unroll
    for (int nt = 0; nt < 16; nt++) { acc[nt][0]=0.f; acc[nt][1]=0.f; acc[nt][2]=0.f; acc[nt][3]=0.f; }

    for (int kc = 0; kc < 4; kc++) {
        __syncthreads();
        #pragma unroll
        for (int j = 0; j < 8; j++) {
            int idx = j*256 + tid; int o = idx >> 3, u = idx & 7;
            *(uint4*)(b_s + o*72 + u*8) =
                *(const uint4*)(WT + (size_t)o*HH + kc*64 + u*8);
        }
        __syncthreads();
        #pragma unroll
        for (int k16 = 0; k16 < 4; k16++) {
            int ka = kc*64 + k16*16;
            uint32_t a[4];
            const __nv_bfloat16* ab = a_s + (size_t)(wm*16)*264 + ka;
            a[0] = *(const uint32_t*)(ab + (size_t)g*264 + t2);
            a[1] = *(const uint32_t*)(ab + (size_t)(g+8)*264 + t2);
            a[2] = *(const uint32_t*)(ab + (size_t)g*264 + t2 + 8);
            a[3] = *(const uint32_t*)(ab + (size_t)(g+8)*264 + t2 + 8);
            int kb = k16*16;
            #pragma unroll
            for (int nt = 0; nt < 16; nt++) {
                const __nv_bfloat16* bb = b_s + (size_t)(wn*128 + nt*8 + g)*72 + kb + t2;
                mma16816(acc[nt], a, *(const uint32_t*)bb, *(const uint32_t*)(bb + 8));
            }
        }
    }

    #pragma unroll
    for (int nt = 0; nt < 16; nt++) {
        int oc = wn*128 + nt*8 + t2;
        float b0v = bi[oc], b1v = bi[oc+1];
        int m0 = r0 + wm*16 + g, m1 = m0 + 8;
        dst[((size_t)(oc & 3)*NN + m0)*HD + (oc >> 2)]         = __float2bfloat16(acc[nt][0] + b0v);
        dst[((size_t)((oc+1) & 3)*NN + m0)*HD + ((oc+1) >> 2)] = __float2bfloat16(acc[nt][1] + b1v);
        dst[((size_t)(oc & 3)*NN + m1)*HD + (oc >> 2)]         = __float2bfloat16(acc[nt][2] + b0v);
        dst[((size_t)((oc+1) & 3)*NN + m1)*HD + ((oc+1) >> 2)] = __float2bfloat16(acc[nt][3] + b1v);
    }
}

// ---------------- fused attention / KL / aggregation (bf16 HMMA) ----------------
#define K_S_ELEMS  (4*32*72)
#define MU_S_ELEMS (4*64*72)
#define HN_S_ELEMS (256*72)
#define BF_ELEMS   (K_S_ELEMS + 2*MU_S_ELEMS + HN_S_ELEMS)
#define EPS_STRIDE 260
#define DIF_STRIDE 68
#define ATTN_SMEM_BYTES (BF_ELEMS*2 + (32*EPS_STRIDE + 32*DIF_STRIDE)*4)

__global__ void __launch_bounds__(256, 1) attn_kernel(const float* __restrict__ diff,
                                                      const float* __restrict__ eps) {
    extern __shared__ __nv_bfloat16 smb[];
    __nv_bfloat16* k_s  = smb;
    __nv_bfloat16* mu_s = k_s + K_S_ELEMS;
    __nv_bfloat16* ls_s = mu_s + MU_S_ELEMS;
    __nv_bfloat16* hn_s = ls_s + MU_S_ELEMS;
    float* eps_s = (float*)(smb + BF_ELEMS);          // [32 x][64 z][4 b], stride 260
    float* dif_s = eps_s + 32*EPS_STRIDE;             // [32 x][64 z], stride 68
    __shared__ float red[8];

    const int tid = threadIdx.x;
    const int xt = blockIdx.x / NSPLIT, sp = blockIdx.x % NSPLIT;
    const int x0 = xt * 32, zbase = sp * ZRANGE;
    const int w = tid >> 5, l = tid & 31;
    const int b = w >> 1, xh = w & 1;
    const int g = l >> 2, t2 = (l & 3) * 2;

    // stage K tile once: 128 rows x 64 bf16 = 8 uint4 per row (FIX: full width)
    #pragma unroll
    for (int j = 0; j < 4; j++) {
        int idx = j*256 + tid; int row = idx >> 3, u = idx & 7;
        int br = row >> 5, xr = row & 31;
        *(uint4*)(k_s + (br*32 + xr)*72 + u*8) =
            *(const uint4*)(g_kt + ((size_t)br*NN + x0 + xr)*HD + u*8);
    }

    float acc[32][4];
    #pragma unroll
    for (int nt = 0; nt < 32; nt++) { acc[nt][0]=0.f; acc[nt][1]=0.f; acc[nt][2]=0.f; acc[nt][3]=0.f; }
    float den0 = 0.f, den1 = 0.f, klloc = 0.f;
    uint32_t kfr[4][4];

    const int xr_lo = x0 + xh*16 + g;

    for (int zi = 0; zi < ZRANGE/64; ++zi) {
        const int zb = zbase + zi*64;
        __syncthreads();
        {   // ---- coalesced staging: mu/ls, hnT, eps, diffusion ----
            #pragma unroll
            for (int j = 0; j < 8; j++) {
                int idx = j*256 + tid; int row = idx >> 3, u = idx & 7;
                int bb = row >> 6, z = row & 63;
                *(uint4*)(mu_s + row*72 + u*8) =
                    *(const uint4*)(g_mut + ((size_t)bb*NN + zb + z)*HD + u*8);
                *(uint4*)(ls_s + row*72 + u*8) =
                    *(const uint4*)(g_lst + ((size_t)bb*NN + zb + z)*HD + u*8);
            }
            #pragma unroll
            for (int j = 0; j < 8; j++) {
                int idx = j*256 + tid; int hr = idx >> 3, u = idx & 7;
                *(uint4*)(hn_s + hr*72 + u*8) =
                    *(const uint4*)(g_hnT + (size_t)hr*NN + zb + u*8);
            }
            #pragma unroll
            for (int j = 0; j < 8; j++) {
                int idx = j*256 + tid; int x = idx >> 6, u = idx & 63;
                *(float4*)(eps_s + x*EPS_STRIDE + u*4) =
                    *(const float4*)(eps + ((size_t)(x0+x)*NN + zb)*4 + u*4);
            }
            #pragma unroll
            for (int j = 0; j < 2; j++) {
                int idx = j*256 + tid; int x = idx >> 4, u = idx & 15;
                *(float4*)(dif_s + x*DIF_STRIDE + u*4) =
                    *(const float4*)(diff + (size_t)(x0+x)*NN + zb + u*4);
            }
        }
        __syncthreads();

        if (zi == 0) {
            #pragma unroll
            for (int kt = 0; kt < 4; kt++) {
                const __nv_bfloat16* base = k_s + (b*32 + xh*16)*72 + kt*16;
                kfr[kt][0] = *(const uint32_t*)(base + (size_t)g*72     + t2);
                kfr[kt][1] = *(const uint32_t*)(base + (size_t)(g+8)*72 + t2);
                kfr[kt][2] = *(const uint32_t*)(base + (size_t)g*72     + t2 + 8);
                kfr[kt][3] = *(const uint32_t*)(base + (size_t)(g+8)*72 + t2 + 8);
            }
        }

        #pragma unroll
        for (int zk = 0; zk < 4; zk++) {
            // ---- score MMAs ----
            float dmu[2][4], dls[2][4];
            #pragma unroll
            for (int t = 0; t < 2; t++) {
                dmu[t][0]=0.f; dmu[t][1]=0.f; dmu[t][2]=0.f; dmu[t][3]=0.f;
                dls[t][0]=0.f; dls[t][1]=0.f; dls[t][2]=0.f; dls[t][3]=0.f;
            }
            #pragma unroll
            for (int kt = 0; kt < 4; kt++) {
                #pragma unroll
                for (int t = 0; t < 2; t++) {
                    int zr = zk*16 + t*8 + g;
                    const __nv_bfloat16* mrow = mu_s + ((size_t)(b*64 + zr))*72 + kt*16 + t2;
                    const __nv_bfloat16* lrow = ls_s + ((size_t)(b*64 + zr))*72 + kt*16 + t2;
                    mma16816(dmu[t], kfr[kt], *(const uint32_t*)mrow, *(const uint32_t*)(mrow + 8));
                    mma16816(dls[t], kfr[kt], *(const uint32_t*)lrow, *(const uint32_t*)(lrow + 8));
                }
            }

            // ---- elementwise: softplus, sample, KL; pack a ----
            uint32_t af[4];
            #pragma unroll
            for (int t = 0; t < 2; t++) {
                #pragma unroll
                for (int rr = 0; rr < 2; rr++) {
                    int lx = xh*16 + rr*8 + g;
                    int lz = zk*16 + t*8 + t2;
                    float2 dv = *(const float2*)(dif_s + lx*DIF_STRIDE + lz);
                    const float* ep = eps_s + lx*EPS_STRIDE + lz*4 + b;
                    float e0 = ep[0], e1 = ep[4];
                    float m0 = dmu[t][rr*2]   * SCALE;
                    float m1 = dmu[t][rr*2+1] * SCALE;
                    float s0 = dls[t][rr*2]   * SCALE;
                    float s1 = dls[t][rr*2+1] * SCALE;
                    float sg0 = __logf(1.f + __expf(s0));
                    float sg1 = __logf(1.f + __expf(s1));
                    float d0 = dv.x, d1 = dv.y;
                    float a0 = __expf(fmaf(sg0, e0, m0)) * d0;
                    float a1 = __expf(fmaf(sg1, e1, m1)) * d1;
                    float sn0 = (d0 > 0.f) ? 1.f : ((d0 < 0.f) ? -1.f : 0.f);
                    float sn1 = (d1 > 0.f) ? 1.f : ((d1 < 0.f) ? -1.f : 0.f);
                    klloc += sn0 * (0.5f*(sg0*sg0 + m0*m0) - 0.5f - __logf(sg0));
                    klloc += sn1 * (0.5f*(sg1*sg1 + m1*m1) - 0.5f - __logf(sg1));
                    if (rr == 0) den0 += a0 + a1; else den1 += a0 + a1;
                    __nv_bfloat162 p = __float22bfloat162_rn(make_float2(a0, a1));
                    af[t*2 + rr] = *(uint32_t*)&p;
                }
            }

            // ---- aggregation MMAs ----
            #pragma unroll
            for (int nt = 0; nt < 32; nt++) {
                const __nv_bfloat16* hrow = hn_s + ((size_t)(nt*8 + g))*72 + zk*16 + t2;
                mma16816(acc[nt], af, *(const uint32_t*)hrow, *(const uint32_t*)(hrow + 8));
            }
        }
    }

    // ---- epilogue ----
    {
        float* outlo = g_accP + ((size_t)sp*NN + xr_lo)*1024 + b*256;
        float* outhi = outlo + (size_t)8*1024;
        #pragma unroll
        for (int nt = 0; nt < 32; nt++) {
            *(float2*)(outlo + nt*8 + t2) = make_float2(acc[nt][0], acc[nt][1]);
            *(float2*)(outhi + nt*8 + t2) = make_float2(acc[nt][2], acc[nt][3]);
        }
        den0 += __shfl_xor_sync(0xffffffffu, den0, 1);
        den0 += __shfl_xor_sync(0xffffffffu, den0, 2);
        den1 += __shfl_xor_sync(0xffffffffu, den1, 1);
        den1 += __shfl_xor_sync(0xffffffffu, den1, 2);
        if ((l & 3) == 0) {
            g_denP[((size_t)sp*NN + xr_lo)*4 + b]     = den0;
            g_denP[((size_t)sp*NN + xr_lo + 8)*4 + b] = den1;
        }
    }
    #pragma unroll
    for (int o = 16; o; o >>= 1) klloc += __shfl_down_sync(0xffffffffu, klloc, o);
    if (l == 0) red[w] = klloc;
    __syncthreads();
    if (tid == 0) {
        float s = 0.f;
        #pragma unroll
        for (int i = 0; i < 8; i++) s += red[i];
        atomicAdd(&g_kl, (double)s);
    }
}

// ---------------- normalize + fc_v (bf16 HMMA) + elu + residual + kl ----------------
#define FIN_SMEM ((16*1032 + 256*72)*2)
__global__ void __launch_bounds__(256) final_kernel(const float* __restrict__ bv,
                                                    const float* __restrict__ h0,
                                                    float* __restrict__ out,
                                                    int out_size) {
    extern __shared__ __nv_bfloat16 fs[];
    __nv_bfloat16* vsb  = fs;             // [16][1032]
    __nv_bfloat16* wv_s = fs + 16*1032;   // [256][72]
    int tid = threadIdx.x;
    int r0 = blockIdx.x * 16;

    // phase 1: sum splits, normalize, convert bf16
    #pragma unroll
    for (int ii = 0; ii < 16; ii++) {
        int idx = ii*256 + tid;
        int r = idx >> 8, c4 = idx & 255;
        int n = r0 + r;
        float4 a0 = *((const float4*)(g_accP + ((size_t)0*NN + n)*1024) + c4);
        float4 a1 = *((const float4*)(g_accP + ((size_t)1*NN + n)*1024) + c4);
        float4 a2 = *((const float4*)(g_accP + ((size_t)2*NN + n)*1024) + c4);
        int b = c4 >> 6;
        float dsum = g_denP[((size_t)0*NN + n)*4 + b]
                   + g_denP[((size_t)1*NN + n)*4 + b]
                   + g_denP[((size_t)2*NN + n)*4 + b];
        float inv = 1.f / fmaxf(dsum, 1e-12f);
        __nv_bfloat162 p0 = __float22bfloat162_rn(make_float2((a0.x+a1.x+a2.x)*inv, (a0.y+a1.y+a2.y)*inv));
        __nv_bfloat162 p1 = __float22bfloat162_rn(make_float2((a0.z+a1.z+a2.z)*inv, (a0.w+a1.w+a2.w)*inv));
        *(uint32_t*)(vsb + r*1032 + c4*4)     = *(uint32_t*)&p0;
        *(uint32_t*)(vsb + r*1032 + c4*4 + 2) = *(uint32_t*)&p1;
    }

    int w = tid >> 5, l = tid & 31, g = l >> 2, t2 = (l & 3)*2;
    int n0 = w * 32;
    float acc[4][4];
    #pragma unroll
    for (int nt = 0; nt < 4; nt++) { acc[nt][0]=0.f; acc[nt][1]=0.f; acc[nt][2]=0.f; acc[nt][3]=0.f; }

    for (int kc = 0; kc < 16; kc++) {
        __syncthreads();
        #pragma unroll
        for (int j = 0; j < 8; j++) {
            int idx = j*256 + tid; int n = idx >> 3, u = idx & 7;
            *(uint4*)(wv_s + n*72 + u*8) =
                *(const uint4*)(g_WvT + (size_t)n*1024 + kc*64 + u*8);
        }
        __syncthreads();
        #pragma unroll
        for (int k16 = 0; k16 < 4; k16++) {
            int ka = kc*64 + k16*16;
            uint32_t a[4];
            a[0] = *(const uint32_t*)(vsb + (size_t)g*1032     + ka + t2);
            a[1] = *(const uint32_t*)(vsb + (size_t)(g+8)*1032 + ka + t2);
            a[2] = *(const uint32_t*)(vsb + (size_t)g*1032     + ka + t2 + 8);
            a[3] = *(const uint32_t*)(vsb + (size_t)(g+8)*1032 + ka + t2 + 8);
            #pragma unroll
            for (int nt = 0; nt < 4; nt++) {
                const __nv_bfloat16* bb = wv_s + (size_t)(n0 + nt*8 + g)*72 + k16*16 + t2;
                mma16816(acc[nt], a, *(const uint32_t*)bb, *(const uint32_t*)(bb + 8));
            }
        }
    }

    // epilogue: bias + elu + residual
    #pragma unroll
    for (int nt = 0; nt < 4; nt++) {
        int oc = n0 + nt*8 + t2;
        float b0v = bv[oc], b1v = bv[oc+1];
        int m0 = r0 + g, m1 = m0 + 8;
        float u00 = acc[nt][0] + b0v, u01 = acc[nt][1] + b1v;
        float u10 = acc[nt][2] + b0v, u11 = acc[nt][3] + b1v;
        u00 = (u00 > 0.f) ? u00 : expm1f(u00);
        u01 = (u01 > 0.f) ? u01 : expm1f(u01);
        u10 = (u10 > 0.f) ? u10 : expm1f(u10);
        u11 = (u11 > 0.f) ? u11 : expm1f(u11);
        float2 hv0 = *(const float2*)(h0 + (size_t)m0*HH + oc);
        float2 hv1 = *(const float2*)(h0 + (size_t)m1*HH + oc);
        *(float2*)(out + (size_t)m0*HH + oc) = make_float2(u00 + hv0.x, u01 + hv0.y);
        *(float2*)(out + (size_t)m1*HH + oc) = make_float2(u10 + hv1.x, u11 + hv1.y);
    }
    if (blockIdx.x == 0 && tid == 0) {
        float klv = (float)(g_kl / ((double)NN * (double)NN));
        for (int i = NHID; i < out_size; i++) out[i] = klv;
    }
}

// ---------------- launch ----------------
extern "C" void kernel_launch(void* const* d_in, const int* in_sizes, int n_in,
                              void* d_out, int out_size) {
    const float* h     = (const float*)d_in[0];
    const float* gamma = (const float*)d_in[1];
    const float* beta  = (const float*)d_in[2];
    const float* Wk    = (const float*)d_in[3];
    const float* bk    = (const float*)d_in[4];
    const float* Wm    = (const float*)d_in[5];
    const float* bm    = (const float*)d_in[6];
    const float* Wl    = (const float*)d_in[7];
    const float* bl    = (const float*)d_in[8];
    const float* Wv    = (const float*)d_in[9];
    const float* bv    = (const float*)d_in[10];
    const float* diff  = (const float*)d_in[11];
    const float* eps   = (const float*)d_in[12];
    float* out = (float*)d_out;

    cudaFuncSetAttribute(attn_kernel, cudaFuncAttributeMaxDynamicSharedMemorySize,
                         ATTN_SMEM_BYTES);
    cudaFuncSetAttribute(proj_kernel, cudaFuncAttributeMaxDynamicSharedMemorySize,
                         PROJ_SMEM);
    cudaFuncSetAttribute(final_kernel, cudaFuncAttributeMaxDynamicSharedMemorySize,
                         FIN_SMEM);

    __nv_bfloat16* WTd;  cudaGetSymbolAddress((void**)&WTd,  g_WT);
    __nv_bfloat16* WvTd; cudaGetSymbolAddress((void**)&WvTd, g_WvT);

    ln_kernel<<<NN, 256>>>(h, gamma, beta);
    dim3 tg(8, 8);
    trans_kernel<<<tg, 256>>>(Wk, WTd,             HH, HH);
    trans_kernel<<<tg, 256>>>(Wm, WTd + HH*HH,     HH, HH);
    trans_kernel<<<tg, 256>>>(Wl, WTd + 2*HH*HH,   HH, HH);
    dim3 tgv(8, 32);
    trans_kernel<<<tgv, 256>>>(Wv, WvTd, 4*HH, HH);
    dim3 gp(NN/64, 3);
    proj_kernel<<<gp, 256, PROJ_SMEM>>>(bk, bm, bl);
    attn_kernel<<<(NN/32)*NSPLIT, 256, ATTN_SMEM_BYTES>>>(diff, eps);
    final_kernel<<<NN/16, 256, FIN_SMEM>>>(bv, h, out, out_size);
}

// round 5
// speedup vs baseline: 5.2452x; 1.3754x over previous
#include <cuda_runtime.h>
#include <cuda_bf16.h>
#include <stdint.h>
#include <math.h>

#define NN 3072
#define HH 256
#define HD 64
#define NHID (NN*HH)
#define NSPLIT 3
#define ZRANGE (NN/NSPLIT)   // 1024
#define SCALE 0.125f         // HD^-0.5

// ---------------- device scratch (static; no allocations) ----------------
__device__ __nv_bfloat16 g_hnB[NHID];                 // hn row-major bf16 (proj A)
__device__ __nv_bfloat16 g_hnT[HH*NN];                // hn transposed [h][n] bf16
__device__ __nv_bfloat16 g_kt[4*NN*HD];               // k  per head [b][n][y]
__device__ __nv_bfloat16 g_mut[4*NN*HD];              // mu per head
__device__ __nv_bfloat16 g_lst[4*NN*HD];              // ls per head
__device__ __nv_bfloat16 g_WT[3*HH*HH];               // W_{k,mu,ls}^T bf16 [o][k]
__device__ __nv_bfloat16 g_WvT[HH*4*HH];              // W_v^T bf16 [256 o][1024 k]
__device__ float g_accP[(size_t)NSPLIT*NN*1024];      // partial agg [sp][n][b*256+h]
__device__ float g_denP[NSPLIT*NN*4];                 // partial denominators
__device__ double g_kl;

// ---------------- PTX helpers ----------------
__device__ __forceinline__ void mma16816(float d[4], const uint32_t a[4],
                                         uint32_t b0, uint32_t b1) {
    asm volatile(
        "mma.sync.aligned.m16n8k16.row.col.f32.bf16.bf16.f32 "
        "{%0,%1,%2,%3},{%4,%5,%6,%7},{%8,%9},{%0,%1,%2,%3};\n"
        : "+f"(d[0]), "+f"(d[1]), "+f"(d[2]), "+f"(d[3])
        : "r"(a[0]), "r"(a[1]), "r"(a[2]), "r"(a[3]), "r"(b0), "r"(b1));
}
__device__ __forceinline__ void ldsm4(uint32_t r[4], uint32_t saddr) {
    asm volatile("ldmatrix.sync.aligned.m8n8.x4.shared.b16 {%0,%1,%2,%3}, [%4];\n"
        : "=r"(r[0]), "=r"(r[1]), "=r"(r[2]), "=r"(r[3]) : "r"(saddr));
}
__device__ __forceinline__ void cp16(uint32_t saddr, const void* g) {
    asm volatile("cp.async.cg.shared.global [%0], [%1], 16;\n" :: "r"(saddr), "l"(g));
}
#define CP_COMMIT() asm volatile("cp.async.commit_group;\n" ::: "memory")
#define CP_WAIT(n)  asm volatile("cp.async.wait_group %0;\n" :: "n"(n) : "memory")
__device__ __forceinline__ uint32_t s32(const void* p) {
    return (uint32_t)__cvta_generic_to_shared(p);
}

// ---------------- prep: LayerNorm + all weight transposes, one launch ----------------
__global__ void __launch_bounds__(256) prep_kernel(const float* __restrict__ h,
                                                   const float* __restrict__ gamma,
                                                   const float* __restrict__ beta,
                                                   const float* __restrict__ Wk,
                                                   const float* __restrict__ Wm,
                                                   const float* __restrict__ Wl,
                                                   const float* __restrict__ Wv) {
    __shared__ float sh[32][33];
    int bx = blockIdx.x, t = threadIdx.x;
    if (bx < NN) {
        // ---- LayerNorm row ----
        int n = bx;
        float v = h[n*HH + t];
        float s = v, q = v*v;
        #pragma unroll
        for (int o = 16; o; o >>= 1) {
            s += __shfl_down_sync(0xffffffffu, s, o);
            q += __shfl_down_sync(0xffffffffu, q, o);
        }
        __shared__ float ss[8], qs[8];
        __shared__ float s_m, s_r;
        int lane = t & 31, w = t >> 5;
        if (lane == 0) { ss[w] = s; qs[w] = q; }
        __syncthreads();
        if (t == 0) {
            float S = 0.f, Q = 0.f;
            #pragma unroll
            for (int i = 0; i < 8; i++) { S += ss[i]; Q += qs[i]; }
            float m = S * (1.f/256.f);
            float var = Q * (1.f/256.f) - m*m;
            s_m = m; s_r = rsqrtf(var + 1e-5f);
        }
        __syncthreads();
        float hn = (v - s_m) * s_r * gamma[t] + beta[t];
        __nv_bfloat16 hb = __float2bfloat16(hn);
        g_hnB[(size_t)n*HH + t] = hb;
        g_hnT[(size_t)t*NN + n] = hb;
        if (n == 0 && t == 0) g_kl = 0.0;
    } else {
        // ---- transpose-convert 32x32 tile ----
        int tb = bx - NN;
        const float* src; __nv_bfloat16* dst; int K, O, o0, k0;
        if (tb < 192) {
            int p = tb >> 6, tl = tb & 63;
            src = (p == 0) ? Wk : (p == 1) ? Wm : Wl;
            dst = g_WT + (size_t)p*HH*HH;
            K = HH; O = HH; o0 = (tl & 7)*32; k0 = (tl >> 3)*32;
        } else {
            int tl = tb - 192;
            src = Wv; dst = g_WvT;
            K = 4*HH; O = HH; o0 = (tl & 7)*32; k0 = (tl >> 3)*32;
        }
        int tx = t & 31, ty = t >> 5;
        #pragma unroll
        for (int j = 0; j < 32; j += 8)
            sh[ty+j][tx] = src[(size_t)(k0+ty+j)*O + o0+tx];
        __syncthreads();
        #pragma unroll
        for (int j = 0; j < 32; j += 8)
            dst[(size_t)(o0+ty+j)*K + k0+tx] = __float2bfloat16(sh[tx][ty+j]);
    }
}

// ---------------- 3 projections (bf16 HMMA) -> head-transposed bf16 ----------------
#define PROJ_SMEM ((64*264 + 256*72)*2)
__global__ void __launch_bounds__(256) proj_kernel(const float* __restrict__ bk,
                                                   const float* __restrict__ bm,
                                                   const float* __restrict__ bl) {
    extern __shared__ __nv_bfloat16 ps[];
    __nv_bfloat16* a_s = ps;            // [64][264]
    __nv_bfloat16* b_s = ps + 64*264;   // [256][72]
    int p = blockIdx.y;
    const __nv_bfloat16* WT = g_WT + (size_t)p*HH*HH;
    const float* bi = (p == 0) ? bk : (p == 1) ? bm : bl;
    __nv_bfloat16* dst = (p == 0) ? g_kt : (p == 1) ? g_mut : g_lst;
    int tid = threadIdx.x;
    int r0 = blockIdx.x * 64;

    #pragma unroll
    for (int j = 0; j < 8; j++) {
        int idx = j*256 + tid; int row = idx >> 5, u = idx & 31;
        *(uint4*)(a_s + row*264 + u*8) =
            *(const uint4*)(g_hnB + (size_t)(r0+row)*HH + u*8);
    }

    int w = tid >> 5, l = tid & 31, t2 = (l & 3)*2, g = l >> 2;
    int wm = w >> 1, wn = w & 1;
    uint32_t a_base = s32(a_s) + (uint32_t)(((wm*16 + (l & 15))*264 + (l >> 4)*8) * 2);
    uint32_t b_base = s32(b_s) + (uint32_t)((((l >> 4)*8 + (l & 7))*72 + ((l >> 3) & 1)*8) * 2);
    float acc[16][4];
    #pragma unroll
    for (int nt = 0; nt < 16; nt++) { acc[nt][0]=0.f; acc[nt][1]=0.f; acc[nt][2]=0.f; acc[nt][3]=0.f; }

    for (int kc = 0; kc < 4; kc++) {
        __syncthreads();
        #pragma unroll
        for (int j = 0; j < 8; j++) {
            int idx = j*256 + tid; int o = idx >> 3, u = idx & 7;
            *(uint4*)(b_s + o*72 + u*8) =
                *(const uint4*)(WT + (size_t)o*HH + kc*64 + u*8);
        }
        __syncthreads();
        #pragma unroll
        for (int k16 = 0; k16 < 4; k16++) {
            uint32_t a[4];
            ldsm4(a, a_base + (uint32_t)((kc*64 + k16*16)*2));
            #pragma unroll
            for (int ntp = 0; ntp < 8; ntp++) {
                uint32_t bb[4];
                ldsm4(bb, b_base + (uint32_t)(((wn*128 + ntp*16)*72 + k16*16)*2));
                mma16816(acc[ntp*2],   a, bb[0], bb[1]);
                mma16816(acc[ntp*2+1], a, bb[2], bb[3]);
            }
        }
    }

    #pragma unroll
    for (int nt = 0; nt < 16; nt++) {
        int oc = wn*128 + nt*8 + t2;
        float b0v = bi[oc], b1v = bi[oc+1];
        int m0 = r0 + wm*16 + g, m1 = m0 + 8;
        dst[((size_t)(oc & 3)*NN + m0)*HD + (oc >> 2)]         = __float2bfloat16(acc[nt][0] + b0v);
        dst[((size_t)((oc+1) & 3)*NN + m0)*HD + ((oc+1) >> 2)] = __float2bfloat16(acc[nt][1] + b1v);
        dst[((size_t)(oc & 3)*NN + m1)*HD + (oc >> 2)]         = __float2bfloat16(acc[nt][2] + b0v);
        dst[((size_t)((oc+1) & 3)*NN + m1)*HD + ((oc+1) >> 2)] = __float2bfloat16(acc[nt][3] + b1v);
    }
}

// ---------------- fused attention / KL / aggregation (LDSM + cp.async pipe) ----------------
#define K_S_ELEMS  (4*32*72)
#define MU_S_ELEMS (4*64*72)
#define HN_S_ELEMS (256*72)
#define BF_ELEMS   (K_S_ELEMS + 2*MU_S_ELEMS + HN_S_ELEMS)
#define EPS_STRIDE 260
#define DIF_STRIDE 68
#define EPS_BUF (32*EPS_STRIDE)
#define DIF_BUF (32*DIF_STRIDE)
#define ATTN_SMEM_BYTES (BF_ELEMS*2 + (2*EPS_BUF + 2*DIF_BUF)*4)

__global__ void __launch_bounds__(256, 1) attn_kernel(const float* __restrict__ diff,
                                                      const float* __restrict__ eps) {
    extern __shared__ __nv_bfloat16 smb[];
    __nv_bfloat16* k_s  = smb;
    __nv_bfloat16* mu_s = k_s + K_S_ELEMS;
    __nv_bfloat16* ls_s = mu_s + MU_S_ELEMS;
    __nv_bfloat16* hn_s = ls_s + MU_S_ELEMS;
    float* eps_s = (float*)(smb + BF_ELEMS);          // 2 x [32][260]
    float* dif_s = eps_s + 2*EPS_BUF;                 // 2 x [32][68]
    __shared__ float red[8];

    const int tid = threadIdx.x;
    const int xt = blockIdx.x / NSPLIT, sp = blockIdx.x % NSPLIT;
    const int x0 = xt * 32, zbase = sp * ZRANGE;
    const int w = tid >> 5, l = tid & 31;
    const int b = w >> 1, xh = w & 1;
    const int g = l >> 2, t2 = (l & 3) * 2;

    // lane-invariant staging indices
    const int sx  = tid >> 6, su  = tid & 63;       // eps: 4 rows x 64 f4
    const int dx  = tid >> 4, du  = tid & 15;       // dif: 16 rows x 16 f4
    const int mrow = tid >> 3, mu8 = tid & 7;       // mu/ls/hn: 32 rows x 8 u4

    // LDSM base addresses
    uint32_t mu_base = s32(mu_s) + (uint32_t)(((b*64 + (l & 7))*72 + (l >> 3)*8) * 2);
    uint32_t ls_base = s32(ls_s) + (uint32_t)(((b*64 + (l & 7))*72 + (l >> 3)*8) * 2);
    uint32_t hn_base = s32(hn_s) + (uint32_t)((((l >> 4)*8 + (l & 7))*72 + ((l >> 3) & 1)*8) * 2);

    // stage K tile once (cp.async, group merged with first staging wait)
    #pragma unroll
    for (int j = 0; j < 4; j++) {
        int idx = j*256 + tid; int row = idx >> 3, u = idx & 7;
        int br = row >> 5, xr = row & 31;
        cp16(s32(k_s + (br*32 + xr)*72 + u*8),
             g_kt + ((size_t)br*NN + x0 + xr)*HD + u*8);
    }
    // prologue: eps/dif for iter 0 into buf 0
    #pragma unroll
    for (int j = 0; j < 8; j++) {
        int idx = j*256 + tid; int x = idx >> 6, u = idx & 63;
        cp16(s32(eps_s + x*EPS_STRIDE + u*4),
             eps + ((size_t)(x0+x)*NN + zbase)*4 + u*4);
    }
    #pragma unroll
    for (int j = 0; j < 2; j++) {
        int idx = j*256 + tid; int x = idx >> 4, u = idx & 15;
        cp16(s32(dif_s + x*DIF_STRIDE + u*4),
             diff + (size_t)(x0+x)*NN + zbase + u*4);
    }
    CP_COMMIT();

    float acc[32][4];
    #pragma unroll
    for (int nt = 0; nt < 32; nt++) { acc[nt][0]=0.f; acc[nt][1]=0.f; acc[nt][2]=0.f; acc[nt][3]=0.f; }
    float den0 = 0.f, den1 = 0.f, klloc = 0.f;
    uint32_t kfr[4][4];
    bool kfr_loaded = false;

    const int xr_lo = x0 + xh*16 + g;

    for (int zi = 0; zi < ZRANGE/64; ++zi) {
        const int zb = zbase + zi*64;
        __syncthreads();   // previous compute done -> smem tiles reusable

        // ---- stage mu/ls/hn via cp.async (group S) ----
        {
            int bb_ = mrow >> 6, z_ = mrow & 63;   // mrow in 0..255? no: 0..31
        }
        #pragma unroll
        for (int j = 0; j < 8; j++) {
            int row = j*32 + mrow;                 // 0..255
            int bb_ = row >> 6, z_ = row & 63;
            cp16(s32(mu_s + row*72 + mu8*8),
                 g_mut + ((size_t)bb_*NN + zb + z_)*HD + mu8*8);
            cp16(s32(ls_s + row*72 + mu8*8),
                 g_lst + ((size_t)bb_*NN + zb + z_)*HD + mu8*8);
            cp16(s32(hn_s + row*72 + mu8*8),
                 g_hnT + (size_t)row*NN + zb + mu8*8);
        }
        CP_COMMIT();   // group S_zi (k_s rides with S_0's wait via earlier commit)

        // ---- prefetch next eps/dif (group E_{zi+1}) ----
        if (zi + 1 < ZRANGE/64) {
            float* enx = eps_s + ((zi+1) & 1)*EPS_BUF;
            float* dnx = dif_s + ((zi+1) & 1)*DIF_BUF;
            int znx = zb + 64;
            #pragma unroll
            for (int j = 0; j < 8; j++) {
                int idx = j*256 + tid; int x = idx >> 6, u = idx & 63;
                cp16(s32(enx + x*EPS_STRIDE + u*4),
                     eps + ((size_t)(x0+x)*NN + znx)*4 + u*4);
            }
            #pragma unroll
            for (int j = 0; j < 2; j++) {
                int idx = j*256 + tid; int x = idx >> 4, u = idx & 15;
                cp16(s32(dnx + x*DIF_STRIDE + u*4),
                     diff + (size_t)(x0+x)*NN + znx + u*4);
            }
            CP_COMMIT();
            CP_WAIT(1);    // S_zi + E_zi done; E_{zi+1} in flight
        } else {
            CP_WAIT(0);
        }
        __syncthreads();

        const float* ecur = eps_s + (zi & 1)*EPS_BUF;
        const float* dcur = dif_s + (zi & 1)*DIF_BUF;

        if (!kfr_loaded) {
            kfr_loaded = true;
            #pragma unroll
            for (int kt = 0; kt < 4; kt++) {
                const __nv_bfloat16* base = k_s + (b*32 + xh*16)*72 + kt*16;
                kfr[kt][0] = *(const uint32_t*)(base + (size_t)g*72     + t2);
                kfr[kt][1] = *(const uint32_t*)(base + (size_t)(g+8)*72 + t2);
                kfr[kt][2] = *(const uint32_t*)(base + (size_t)g*72     + t2 + 8);
                kfr[kt][3] = *(const uint32_t*)(base + (size_t)(g+8)*72 + t2 + 8);
            }
        }

        #pragma unroll
        for (int zk = 0; zk < 4; zk++) {
            // ---- score MMAs (B via LDSM.x4) ----
            float dmu[2][4], dls[2][4];
            #pragma unroll
            for (int t = 0; t < 2; t++) {
                dmu[t][0]=0.f; dmu[t][1]=0.f; dmu[t][2]=0.f; dmu[t][3]=0.f;
                dls[t][0]=0.f; dls[t][1]=0.f; dls[t][2]=0.f; dls[t][3]=0.f;
                uint32_t roff = (uint32_t)(((zk*16 + t*8)*72) * 2);
                uint32_t mb[4], lb[4];
                ldsm4(mb, mu_base + roff);
                mma16816(dmu[t], kfr[0], mb[0], mb[1]);
                mma16816(dmu[t], kfr[1], mb[2], mb[3]);
                ldsm4(mb, mu_base + roff + 64);   // +32 bf16
                mma16816(dmu[t], kfr[2], mb[0], mb[1]);
                mma16816(dmu[t], kfr[3], mb[2], mb[3]);
                ldsm4(lb, ls_base + roff);
                mma16816(dls[t], kfr[0], lb[0], lb[1]);
                mma16816(dls[t], kfr[1], lb[2], lb[3]);
                ldsm4(lb, ls_base + roff + 64);
                mma16816(dls[t], kfr[2], lb[0], lb[1]);
                mma16816(dls[t], kfr[3], lb[2], lb[3]);
            }

            // ---- elementwise ----
            uint32_t af[4];
            #pragma unroll
            for (int t = 0; t < 2; t++) {
                #pragma unroll
                for (int rr = 0; rr < 2; rr++) {
                    int lx = xh*16 + rr*8 + g;
                    int lz = zk*16 + t*8 + t2;
                    float2 dv = *(const float2*)(dcur + lx*DIF_STRIDE + lz);
                    const float* ep = ecur + lx*EPS_STRIDE + lz*4 + b;
                    float e0 = ep[0], e1 = ep[4];
                    float m0 = dmu[t][rr*2]   * SCALE;
                    float m1 = dmu[t][rr*2+1] * SCALE;
                    float s0 = dls[t][rr*2]   * SCALE;
                    float s1 = dls[t][rr*2+1] * SCALE;
                    float sg0 = __logf(1.f + __expf(s0));
                    float sg1 = __logf(1.f + __expf(s1));
                    float d0 = dv.x, d1 = dv.y;
                    float a0 = __expf(fmaf(sg0, e0, m0)) * d0;
                    float a1 = __expf(fmaf(sg1, e1, m1)) * d1;
                    float sn0 = (d0 > 0.f) ? 1.f : ((d0 < 0.f) ? -1.f : 0.f);
                    float sn1 = (d1 > 0.f) ? 1.f : ((d1 < 0.f) ? -1.f : 0.f);
                    klloc += sn0 * (0.5f*(sg0*sg0 + m0*m0) - 0.5f - __logf(sg0));
                    klloc += sn1 * (0.5f*(sg1*sg1 + m1*m1) - 0.5f - __logf(sg1));
                    if (rr == 0) den0 += a0 + a1; else den1 += a0 + a1;
                    __nv_bfloat162 p = __float22bfloat162_rn(make_float2(a0, a1));
                    af[t*2 + rr] = *(uint32_t*)&p;
                }
            }

            // ---- aggregation MMAs (B via LDSM.x4, 2 tiles each) ----
            uint32_t zoff = (uint32_t)((zk*16)*2);
            #pragma unroll
            for (int ntp = 0; ntp < 16; ntp++) {
                uint32_t hb[4];
                ldsm4(hb, hn_base + (uint32_t)((ntp*16*72)*2) + zoff);
                mma16816(acc[ntp*2],   af, hb[0], hb[1]);
                mma16816(acc[ntp*2+1], af, hb[2], hb[3]);
            }
        }
    }

    // ---- epilogue ----
    {
        float* outlo = g_accP + ((size_t)sp*NN + xr_lo)*1024 + b*256;
        float* outhi = outlo + (size_t)8*1024;
        #pragma unroll
        for (int nt = 0; nt < 32; nt++) {
            *(float2*)(outlo + nt*8 + t2) = make_float2(acc[nt][0], acc[nt][1]);
            *(float2*)(outhi + nt*8 + t2) = make_float2(acc[nt][2], acc[nt][3]);
        }
        den0 += __shfl_xor_sync(0xffffffffu, den0, 1);
        den0 += __shfl_xor_sync(0xffffffffu, den0, 2);
        den1 += __shfl_xor_sync(0xffffffffu, den1, 1);
        den1 += __shfl_xor_sync(0xffffffffu, den1, 2);
        if ((l & 3) == 0) {
            g_denP[((size_t)sp*NN + xr_lo)*4 + b]     = den0;
            g_denP[((size_t)sp*NN + xr_lo + 8)*4 + b] = den1;
        }
    }
    #pragma unroll
    for (int o = 16; o; o >>= 1) klloc += __shfl_down_sync(0xffffffffu, klloc, o);
    if (l == 0) red[w] = klloc;
    __syncthreads();
    if (tid == 0) {
        float s = 0.f;
        #pragma unroll
        for (int i = 0; i < 8; i++) s += red[i];
        atomicAdd(&g_kl, (double)s);
    }
}

// ---------------- normalize + fc_v (bf16 HMMA, LDSM) + elu + residual + kl ----------------
#define FIN_SMEM ((16*1032 + 256*72)*2)
__global__ void __launch_bounds__(256) final_kernel(const float* __restrict__ bv,
                                                    const float* __restrict__ h0,
                                                    float* __restrict__ out,
                                                    int out_size) {
    extern __shared__ __nv_bfloat16 fs[];
    __nv_bfloat16* vsb  = fs;             // [16][1032]
    __nv_bfloat16* wv_s = fs + 16*1032;   // [256][72]
    int tid = threadIdx.x;
    int r0 = blockIdx.x * 16;

    #pragma unroll
    for (int ii = 0; ii < 16; ii++) {
        int idx = ii*256 + tid;
        int r = idx >> 8, c4 = idx & 255;
        int n = r0 + r;
        float4 a0 = *((const float4*)(g_accP + ((size_t)0*NN + n)*1024) + c4);
        float4 a1 = *((const float4*)(g_accP + ((size_t)1*NN + n)*1024) + c4);
        float4 a2 = *((const float4*)(g_accP + ((size_t)2*NN + n)*1024) + c4);
        int b = c4 >> 6;
        float dsum = g_denP[((size_t)0*NN + n)*4 + b]
                   + g_denP[((size_t)1*NN + n)*4 + b]
                   + g_denP[((size_t)2*NN + n)*4 + b];
        float inv = 1.f / fmaxf(dsum, 1e-12f);
        __nv_bfloat162 p0 = __float22bfloat162_rn(make_float2((a0.x+a1.x+a2.x)*inv, (a0.y+a1.y+a2.y)*inv));
        __nv_bfloat162 p1 = __float22bfloat162_rn(make_float2((a0.z+a1.z+a2.z)*inv, (a0.w+a1.w+a2.w)*inv));
        *(uint32_t*)(vsb + r*1032 + c4*4)     = *(uint32_t*)&p0;
        *(uint32_t*)(vsb + r*1032 + c4*4 + 2) = *(uint32_t*)&p1;
    }

    int w = tid >> 5, l = tid & 31, g = l >> 2, t2 = (l & 3)*2;
    int n0 = w * 32;
    uint32_t a_base = s32(vsb)  + (uint32_t)(((l & 15)*1032 + (l >> 4)*8) * 2);
    uint32_t b_base = s32(wv_s) + (uint32_t)((((l >> 4)*8 + (l & 7))*72 + ((l >> 3) & 1)*8) * 2);
    float acc[4][4];
    #pragma unroll
    for (int nt = 0; nt < 4; nt++) { acc[nt][0]=0.f; acc[nt][1]=0.f; acc[nt][2]=0.f; acc[nt][3]=0.f; }

    for (int kc = 0; kc < 16; kc++) {
        __syncthreads();
        #pragma unroll
        for (int j = 0; j < 8; j++) {
            int idx = j*256 + tid; int n = idx >> 3, u = idx & 7;
            *(uint4*)(wv_s + n*72 + u*8) =
                *(const uint4*)(g_WvT + (size_t)n*1024 + kc*64 + u*8);
        }
        __syncthreads();
        #pragma unroll
        for (int k16 = 0; k16 < 4; k16++) {
            uint32_t a[4];
            ldsm4(a, a_base + (uint32_t)((kc*64 + k16*16)*2));
            #pragma unroll
            for (int ntp = 0; ntp < 2; ntp++) {
                uint32_t bb[4];
                ldsm4(bb, b_base + (uint32_t)(((n0 + ntp*16)*72 + k16*16)*2));
                mma16816(acc[ntp*2],   a, bb[0], bb[1]);
                mma16816(acc[ntp*2+1], a, bb[2], bb[3]);
            }
        }
    }

    #pragma unroll
    for (int nt = 0; nt < 4; nt++) {
        int oc = n0 + nt*8 + t2;
        float b0v = bv[oc], b1v = bv[oc+1];
        int m0 = r0 + g, m1 = m0 + 8;
        float u00 = acc[nt][0] + b0v, u01 = acc[nt][1] + b1v;
        float u10 = acc[nt][2] + b0v, u11 = acc[nt][3] + b1v;
        u00 = (u00 > 0.f) ? u00 : expm1f(u00);
        u01 = (u01 > 0.f) ? u01 : expm1f(u01);
        u10 = (u10 > 0.f) ? u10 : expm1f(u10);
        u11 = (u11 > 0.f) ? u11 : expm1f(u11);
        float2 hv0 = *(const float2*)(h0 + (size_t)m0*HH + oc);
        float2 hv1 = *(const float2*)(h0 + (size_t)m1*HH + oc);
        *(float2*)(out + (size_t)m0*HH + oc) = make_float2(u00 + hv0.x, u01 + hv0.y);
        *(float2*)(out + (size_t)m1*HH + oc) = make_float2(u10 + hv1.x, u11 + hv1.y);
    }
    if (blockIdx.x == 0 && tid == 0) {
        float klv = (float)(g_kl / ((double)NN * (double)NN));
        for (int i = NHID; i < out_size; i++) out[i] = klv;
    }
}

// ---------------- launch ----------------
extern "C" void kernel_launch(void* const* d_in, const int* in_sizes, int n_in,
                              void* d_out, int out_size) {
    const float* h     = (const float*)d_in[0];
    const float* gamma = (const float*)d_in[1];
    const float* beta  = (const float*)d_in[2];
    const float* Wk    = (const float*)d_in[3];
    const float* bk    = (const float*)d_in[4];
    const float* Wm    = (const float*)d_in[5];
    const float* bm    = (const float*)d_in[6];
    const float* Wl    = (const float*)d_in[7];
    const float* bl    = (const float*)d_in[8];
    const float* Wv    = (const float*)d_in[9];
    const float* bv    = (const float*)d_in[10];
    const float* diff  = (const float*)d_in[11];
    const float* eps   = (const float*)d_in[12];
    float* out = (float*)d_out;

    cudaFuncSetAttribute(attn_kernel, cudaFuncAttributeMaxDynamicSharedMemorySize,
                         ATTN_SMEM_BYTES);
    cudaFuncSetAttribute(proj_kernel, cudaFuncAttributeMaxDynamicSharedMemorySize,
                         PROJ_SMEM);
    cudaFuncSetAttribute(final_kernel, cudaFuncAttributeMaxDynamicSharedMemorySize,
                         FIN_SMEM);

    prep_kernel<<<NN + 192 + 256, 256>>>(h, gamma, beta, Wk, Wm, Wl, Wv);
    dim3 gp(NN/64, 3);
    proj_kernel<<<gp, 256, PROJ_SMEM>>>(bk, bm, bl);
    attn_kernel<<<(NN/32)*NSPLIT, 256, ATTN_SMEM_BYTES>>>(diff, eps);
    final_kernel<<<NN/16, 256, FIN_SMEM>>>(bv, h, out, out_size);
}

// round 6
// speedup vs baseline: 5.4359x; 1.0364x over previous
#include <cuda_runtime.h>
#include <cuda_bf16.h>
#include <stdint.h>
#include <math.h>

#define NN 3072
#define HH 256
#define HD 64
#define NHID (NN*HH)
#define NSPLIT 3
#define ZRANGE (NN/NSPLIT)   // 1024
#define SCALE 0.125f         // HD^-0.5

// ---------------- device scratch (static; no allocations) ----------------
__device__ __nv_bfloat16 g_hnB[NHID];                 // hn row-major bf16 (proj A)
__device__ __nv_bfloat16 g_hnT[HH*NN];                // hn transposed [h][n] bf16
__device__ __nv_bfloat16 g_kt[4*NN*HD];               // k  per head [b][n][y]
__device__ __nv_bfloat16 g_mut[4*NN*HD];              // mu per head
__device__ __nv_bfloat16 g_lst[4*NN*HD];              // ls per head
__device__ __nv_bfloat16 g_WT[3*HH*HH];               // W_{k,mu,ls}^T bf16 [o][k]
__device__ __nv_bfloat16 g_WvT[HH*4*HH];              // W_v^T bf16 [256 o][1024 k]
__device__ float g_acc[(size_t)NN*1024];              // agg accumulator [n][b*256+h]
__device__ float g_den[NN*4];                         // denominators [n][b]
__device__ double g_kl;

// ---------------- PTX helpers ----------------
__device__ __forceinline__ void mma16816(float d[4], const uint32_t a[4],
                                         uint32_t b0, uint32_t b1) {
    asm volatile(
        "mma.sync.aligned.m16n8k16.row.col.f32.bf16.bf16.f32 "
        "{%0,%1,%2,%3},{%4,%5,%6,%7},{%8,%9},{%0,%1,%2,%3};\n"
        : "+f"(d[0]), "+f"(d[1]), "+f"(d[2]), "+f"(d[3])
        : "r"(a[0]), "r"(a[1]), "r"(a[2]), "r"(a[3]), "r"(b0), "r"(b1));
}
__device__ __forceinline__ void ldsm4(uint32_t r[4], uint32_t saddr) {
    asm volatile("ldmatrix.sync.aligned.m8n8.x4.shared.b16 {%0,%1,%2,%3}, [%4];\n"
        : "=r"(r[0]), "=r"(r[1]), "=r"(r[2]), "=r"(r[3]) : "r"(saddr));
}
__device__ __forceinline__ void cp16(uint32_t saddr, const void* g) {
    asm volatile("cp.async.cg.shared.global [%0], [%1], 16;\n" :: "r"(saddr), "l"(g));
}
#define CP_COMMIT() asm volatile("cp.async.commit_group;\n" ::: "memory")
#define CP_WAIT(n)  asm volatile("cp.async.wait_group %0;\n" :: "n"(n) : "memory")
__device__ __forceinline__ uint32_t s32(const void* p) {
    return (uint32_t)__cvta_generic_to_shared(p);
}

// ---------------- prep: LayerNorm + weight transposes + accumulator zeroing ----------------
__global__ void __launch_bounds__(256) prep_kernel(const float* __restrict__ h,
                                                   const float* __restrict__ gamma,
                                                   const float* __restrict__ beta,
                                                   const float* __restrict__ Wk,
                                                   const float* __restrict__ Wm,
                                                   const float* __restrict__ Wl,
                                                   const float* __restrict__ Wv) {
    __shared__ float sh[32][33];
    int bx = blockIdx.x, t = threadIdx.x;
    if (bx < NN) {
        int n = bx;
        // zero accumulator row (consumed by attn atomics)
        *(float4*)(g_acc + (size_t)n*1024 + t*4) = make_float4(0.f,0.f,0.f,0.f);
        if (t == 0) *(float4*)(g_den + n*4) = make_float4(0.f,0.f,0.f,0.f);
        // ---- LayerNorm row ----
        float v = h[n*HH + t];
        float s = v, q = v*v;
        #pragma unroll
        for (int o = 16; o; o >>= 1) {
            s += __shfl_down_sync(0xffffffffu, s, o);
            q += __shfl_down_sync(0xffffffffu, q, o);
        }
        __shared__ float ss[8], qs[8];
        __shared__ float s_m, s_r;
        int lane = t & 31, w = t >> 5;
        if (lane == 0) { ss[w] = s; qs[w] = q; }
        __syncthreads();
        if (t == 0) {
            float S = 0.f, Q = 0.f;
            #pragma unroll
            for (int i = 0; i < 8; i++) { S += ss[i]; Q += qs[i]; }
            float m = S * (1.f/256.f);
            float var = Q * (1.f/256.f) - m*m;
            s_m = m; s_r = rsqrtf(var + 1e-5f);
        }
        __syncthreads();
        float hn = (v - s_m) * s_r * gamma[t] + beta[t];
        __nv_bfloat16 hb = __float2bfloat16(hn);
        g_hnB[(size_t)n*HH + t] = hb;
        g_hnT[(size_t)t*NN + n] = hb;
        if (n == 0 && t == 0) g_kl = 0.0;
    } else {
        // ---- transpose-convert 32x32 tile ----
        int tb = bx - NN;
        const float* src; __nv_bfloat16* dst; int K, O, o0, k0;
        if (tb < 192) {
            int p = tb >> 6, tl = tb & 63;
            src = (p == 0) ? Wk : (p == 1) ? Wm : Wl;
            dst = g_WT + (size_t)p*HH*HH;
            K = HH; O = HH; o0 = (tl & 7)*32; k0 = (tl >> 3)*32;
        } else {
            int tl = tb - 192;
            src = Wv; dst = g_WvT;
            K = 4*HH; O = HH; o0 = (tl & 7)*32; k0 = (tl >> 3)*32;
        }
        int tx = t & 31, ty = t >> 5;
        #pragma unroll
        for (int j = 0; j < 32; j += 8)
            sh[ty+j][tx] = src[(size_t)(k0+ty+j)*O + o0+tx];
        __syncthreads();
        #pragma unroll
        for (int j = 0; j < 32; j += 8)
            dst[(size_t)(o0+ty+j)*K + k0+tx] = __float2bfloat16(sh[tx][ty+j]);
    }
}

// ---------------- 3 projections (bf16 HMMA) -> head-transposed bf16 ----------------
#define PROJ_SMEM ((64*264 + 256*72)*2)
__global__ void __launch_bounds__(256) proj_kernel(const float* __restrict__ bk,
                                                   const float* __restrict__ bm,
                                                   const float* __restrict__ bl) {
    extern __shared__ __nv_bfloat16 ps[];
    __nv_bfloat16* a_s = ps;            // [64][264]
    __nv_bfloat16* b_s = ps + 64*264;   // [256][72]
    int p = blockIdx.y;
    const __nv_bfloat16* WT = g_WT + (size_t)p*HH*HH;
    const float* bi = (p == 0) ? bk : (p == 1) ? bm : bl;
    __nv_bfloat16* dst = (p == 0) ? g_kt : (p == 1) ? g_mut : g_lst;
    int tid = threadIdx.x;
    int r0 = blockIdx.x * 64;

    #pragma unroll
    for (int j = 0; j < 8; j++) {
        int idx = j*256 + tid; int row = idx >> 5, u = idx & 31;
        *(uint4*)(a_s + row*264 + u*8) =
            *(const uint4*)(g_hnB + (size_t)(r0+row)*HH + u*8);
    }

    int w = tid >> 5, l = tid & 31, t2 = (l & 3)*2, g = l >> 2;
    int wm = w >> 1, wn = w & 1;
    uint32_t a_base = s32(a_s) + (uint32_t)(((wm*16 + (l & 15))*264 + (l >> 4)*8) * 2);
    uint32_t b_base = s32(b_s) + (uint32_t)((((l >> 4)*8 + (l & 7))*72 + ((l >> 3) & 1)*8) * 2);
    float acc[16][4];
    #pragma unroll
    for (int nt = 0; nt < 16; nt++) { acc[nt][0]=0.f; acc[nt][1]=0.f; acc[nt][2]=0.f; acc[nt][3]=0.f; }

    for (int kc = 0; kc < 4; kc++) {
        __syncthreads();
        #pragma unroll
        for (int j = 0; j < 8; j++) {
            int idx = j*256 + tid; int o = idx >> 3, u = idx & 7;
            *(uint4*)(b_s + o*72 + u*8) =
                *(const uint4*)(WT + (size_t)o*HH + kc*64 + u*8);
        }
        __syncthreads();
        #pragma unroll
        for (int k16 = 0; k16 < 4; k16++) {
            uint32_t a[4];
            ldsm4(a, a_base + (uint32_t)((kc*64 + k16*16)*2));
            #pragma unroll
            for (int ntp = 0; ntp < 8; ntp++) {
                uint32_t bb[4];
                ldsm4(bb, b_base + (uint32_t)(((wn*128 + ntp*16)*72 + k16*16)*2));
                mma16816(acc[ntp*2],   a, bb[0], bb[1]);
                mma16816(acc[ntp*2+1], a, bb[2], bb[3]);
            }
        }
    }

    #pragma unroll
    for (int nt = 0; nt < 16; nt++) {
        int oc = wn*128 + nt*8 + t2;
        float b0v = bi[oc], b1v = bi[oc+1];
        int m0 = r0 + wm*16 + g, m1 = m0 + 8;
        dst[((size_t)(oc & 3)*NN + m0)*HD + (oc >> 2)]         = __float2bfloat16(acc[nt][0] + b0v);
        dst[((size_t)((oc+1) & 3)*NN + m0)*HD + ((oc+1) >> 2)] = __float2bfloat16(acc[nt][1] + b1v);
        dst[((size_t)(oc & 3)*NN + m1)*HD + (oc >> 2)]         = __float2bfloat16(acc[nt][2] + b0v);
        dst[((size_t)((oc+1) & 3)*NN + m1)*HD + ((oc+1) >> 2)] = __float2bfloat16(acc[nt][3] + b1v);
    }
}

// ---------------- fused attention / KL / aggregation (LDSM + cp.async pipe) ----------------
#define K_S_ELEMS  (4*32*72)
#define MU_S_ELEMS (4*64*72)
#define HN_S_ELEMS (256*72)
#define BF_ELEMS   (K_S_ELEMS + 2*MU_S_ELEMS + HN_S_ELEMS)
#define EPS_STRIDE 260
#define DIF_STRIDE 68
#define EPS_BUF (32*EPS_STRIDE)
#define DIF_BUF (32*DIF_STRIDE)
#define ATTN_SMEM_BYTES (BF_ELEMS*2 + (2*EPS_BUF + 2*DIF_BUF)*4)

__global__ void __launch_bounds__(256, 1) attn_kernel(const float* __restrict__ diff,
                                                      const float* __restrict__ eps) {
    extern __shared__ __nv_bfloat16 smb[];
    __nv_bfloat16* k_s  = smb;
    __nv_bfloat16* mu_s = k_s + K_S_ELEMS;
    __nv_bfloat16* ls_s = mu_s + MU_S_ELEMS;
    __nv_bfloat16* hn_s = ls_s + MU_S_ELEMS;
    float* eps_s = (float*)(smb + BF_ELEMS);          // 2 x [32][260]
    float* dif_s = eps_s + 2*EPS_BUF;                 // 2 x [32][68]
    __shared__ float red[8];

    const int tid = threadIdx.x;
    const int xt = blockIdx.x / NSPLIT, sp = blockIdx.x % NSPLIT;
    const int x0 = xt * 32, zbase = sp * ZRANGE;
    const int w = tid >> 5, l = tid & 31;
    const int b = w >> 1, xh = w & 1;
    const int g = l >> 2, t2 = (l & 3) * 2;

    const int mrow = tid >> 3, mu8 = tid & 7;       // mu/ls/hn staging: rows x 8 u4

    uint32_t mu_base = s32(mu_s) + (uint32_t)(((b*64 + (l & 7))*72 + (l >> 3)*8) * 2);
    uint32_t ls_base = s32(ls_s) + (uint32_t)(((b*64 + (l & 7))*72 + (l >> 3)*8) * 2);
    uint32_t hn_base = s32(hn_s) + (uint32_t)((((l >> 4)*8 + (l & 7))*72 + ((l >> 3) & 1)*8) * 2);

    // stage K tile once
    #pragma unroll
    for (int j = 0; j < 4; j++) {
        int idx = j*256 + tid; int row = idx >> 3, u = idx & 7;
        int br = row >> 5, xr = row & 31;
        cp16(s32(k_s + (br*32 + xr)*72 + u*8),
             g_kt + ((size_t)br*NN + x0 + xr)*HD + u*8);
    }
    // prologue: eps/dif for iter 0 into buf 0
    #pragma unroll
    for (int j = 0; j < 8; j++) {
        int idx = j*256 + tid; int x = idx >> 6, u = idx & 63;
        cp16(s32(eps_s + x*EPS_STRIDE + u*4),
             eps + ((size_t)(x0+x)*NN + zbase)*4 + u*4);
    }
    #pragma unroll
    for (int j = 0; j < 2; j++) {
        int idx = j*256 + tid; int x = idx >> 4, u = idx & 15;
        cp16(s32(dif_s + x*DIF_STRIDE + u*4),
             diff + (size_t)(x0+x)*NN + zbase + u*4);
    }
    CP_COMMIT();

    float acc[32][4];
    #pragma unroll
    for (int nt = 0; nt < 32; nt++) { acc[nt][0]=0.f; acc[nt][1]=0.f; acc[nt][2]=0.f; acc[nt][3]=0.f; }
    float den0 = 0.f, den1 = 0.f, klloc = 0.f;
    uint32_t kfr[4][4];
    bool kfr_loaded = false;

    const int xr_lo = x0 + xh*16 + g;

    for (int zi = 0; zi < ZRANGE/64; ++zi) {
        const int zb = zbase + zi*64;
        __syncthreads();   // previous compute done -> smem tiles reusable

        // ---- stage mu/ls/hn via cp.async ----
        #pragma unroll
        for (int j = 0; j < 8; j++) {
            int row = j*32 + mrow;                 // 0..255
            int bb_ = row >> 6, z_ = row & 63;
            cp16(s32(mu_s + row*72 + mu8*8),
                 g_mut + ((size_t)bb_*NN + zb + z_)*HD + mu8*8);
            cp16(s32(ls_s + row*72 + mu8*8),
                 g_lst + ((size_t)bb_*NN + zb + z_)*HD + mu8*8);
            cp16(s32(hn_s + row*72 + mu8*8),
                 g_hnT + (size_t)row*NN + zb + mu8*8);
        }
        CP_COMMIT();

        // ---- prefetch next eps/dif ----
        if (zi + 1 < ZRANGE/64) {
            float* enx = eps_s + ((zi+1) & 1)*EPS_BUF;
            float* dnx = dif_s + ((zi+1) & 1)*DIF_BUF;
            int znx = zb + 64;
            #pragma unroll
            for (int j = 0; j < 8; j++) {
                int idx = j*256 + tid; int x = idx >> 6, u = idx & 63;
                cp16(s32(enx + x*EPS_STRIDE + u*4),
                     eps + ((size_t)(x0+x)*NN + znx)*4 + u*4);
            }
            #pragma unroll
            for (int j = 0; j < 2; j++) {
                int idx = j*256 + tid; int x = idx >> 4, u = idx & 15;
                cp16(s32(dnx + x*DIF_STRIDE + u*4),
                     diff + (size_t)(x0+x)*NN + znx + u*4);
            }
            CP_COMMIT();
            CP_WAIT(1);
        } else {
            CP_WAIT(0);
        }
        __syncthreads();

        const float* ecur = eps_s + (zi & 1)*EPS_BUF;
        const float* dcur = dif_s + (zi & 1)*DIF_BUF;

        if (!kfr_loaded) {
            kfr_loaded = true;
            #pragma unroll
            for (int kt = 0; kt < 4; kt++) {
                const __nv_bfloat16* base = k_s + (b*32 + xh*16)*72 + kt*16;
                kfr[kt][0] = *(const uint32_t*)(base + (size_t)g*72     + t2);
                kfr[kt][1] = *(const uint32_t*)(base + (size_t)(g+8)*72 + t2);
                kfr[kt][2] = *(const uint32_t*)(base + (size_t)g*72     + t2 + 8);
                kfr[kt][3] = *(const uint32_t*)(base + (size_t)(g+8)*72 + t2 + 8);
            }
        }

        #pragma unroll
        for (int zk = 0; zk < 4; zk++) {
            // ---- score MMAs (B via LDSM.x4) ----
            float dmu[2][4], dls[2][4];
            #pragma unroll
            for (int t = 0; t < 2; t++) {
                dmu[t][0]=0.f; dmu[t][1]=0.f; dmu[t][2]=0.f; dmu[t][3]=0.f;
                dls[t][0]=0.f; dls[t][1]=0.f; dls[t][2]=0.f; dls[t][3]=0.f;
                uint32_t roff = (uint32_t)(((zk*16 + t*8)*72) * 2);
                uint32_t mb[4], lb[4];
                ldsm4(mb, mu_base + roff);
                mma16816(dmu[t], kfr[0], mb[0], mb[1]);
                mma16816(dmu[t], kfr[1], mb[2], mb[3]);
                ldsm4(mb, mu_base + roff + 64);
                mma16816(dmu[t], kfr[2], mb[0], mb[1]);
                mma16816(dmu[t], kfr[3], mb[2], mb[3]);
                ldsm4(lb, ls_base + roff);
                mma16816(dls[t], kfr[0], lb[0], lb[1]);
                mma16816(dls[t], kfr[1], lb[2], lb[3]);
                ldsm4(lb, ls_base + roff + 64);
                mma16816(dls[t], kfr[2], lb[0], lb[1]);
                mma16816(dls[t], kfr[3], lb[2], lb[3]);
            }

            // ---- elementwise ----
            uint32_t af[4];
            #pragma unroll
            for (int t = 0; t < 2; t++) {
                #pragma unroll
                for (int rr = 0; rr < 2; rr++) {
                    int lx = xh*16 + rr*8 + g;
                    int lz = zk*16 + t*8 + t2;
                    float2 dv = *(const float2*)(dcur + lx*DIF_STRIDE + lz);
                    const float* ep = ecur + lx*EPS_STRIDE + lz*4 + b;
                    float e0 = ep[0], e1 = ep[4];
                    float m0 = dmu[t][rr*2]   * SCALE;
                    float m1 = dmu[t][rr*2+1] * SCALE;
                    float s0 = dls[t][rr*2]   * SCALE;
                    float s1 = dls[t][rr*2+1] * SCALE;
                    float sg0 = __logf(1.f + __expf(s0));
                    float sg1 = __logf(1.f + __expf(s1));
                    float d0 = dv.x, d1 = dv.y;
                    float a0 = __expf(fmaf(sg0, e0, m0)) * d0;
                    float a1 = __expf(fmaf(sg1, e1, m1)) * d1;
                    float sn0 = (d0 > 0.f) ? 1.f : ((d0 < 0.f) ? -1.f : 0.f);
                    float sn1 = (d1 > 0.f) ? 1.f : ((d1 < 0.f) ? -1.f : 0.f);
                    klloc += sn0 * (0.5f*(sg0*sg0 + m0*m0) - 0.5f - __logf(sg0));
                    klloc += sn1 * (0.5f*(sg1*sg1 + m1*m1) - 0.5f - __logf(sg1));
                    if (rr == 0) den0 += a0 + a1; else den1 += a0 + a1;
                    __nv_bfloat162 p = __float22bfloat162_rn(make_float2(a0, a1));
                    af[t*2 + rr] = *(uint32_t*)&p;
                }
            }

            // ---- aggregation MMAs ----
            uint32_t zoff = (uint32_t)((zk*16)*2);
            #pragma unroll
            for (int ntp = 0; ntp < 16; ntp++) {
                uint32_t hb[4];
                ldsm4(hb, hn_base + (uint32_t)((ntp*16*72)*2) + zoff);
                mma16816(acc[ntp*2],   af, hb[0], hb[1]);
                mma16816(acc[ntp*2+1], af, hb[2], hb[3]);
            }
        }
    }

    // ---- epilogue: atomic accumulation (RED.E.ADD.F32, no readback) ----
    {
        float* outlo = g_acc + (size_t)xr_lo*1024 + b*256;
        float* outhi = outlo + (size_t)8*1024;
        #pragma unroll
        for (int nt = 0; nt < 32; nt++) {
            atomicAdd(outlo + nt*8 + t2,     acc[nt][0]);
            atomicAdd(outlo + nt*8 + t2 + 1, acc[nt][1]);
            atomicAdd(outhi + nt*8 + t2,     acc[nt][2]);
            atomicAdd(outhi + nt*8 + t2 + 1, acc[nt][3]);
        }
        den0 += __shfl_xor_sync(0xffffffffu, den0, 1);
        den0 += __shfl_xor_sync(0xffffffffu, den0, 2);
        den1 += __shfl_xor_sync(0xffffffffu, den1, 1);
        den1 += __shfl_xor_sync(0xffffffffu, den1, 2);
        if ((l & 3) == 0) {
            atomicAdd(g_den + xr_lo*4 + b,       den0);
            atomicAdd(g_den + (xr_lo + 8)*4 + b, den1);
        }
    }
    #pragma unroll
    for (int o = 16; o; o >>= 1) klloc += __shfl_down_sync(0xffffffffu, klloc, o);
    if (l == 0) red[w] = klloc;
    __syncthreads();
    if (tid == 0) {
        float s = 0.f;
        #pragma unroll
        for (int i = 0; i < 8; i++) s += red[i];
        atomicAdd(&g_kl, (double)s);
    }
}

// ---------------- normalize + fc_v (bf16 HMMA, cp.async double-buffer) ----------------
#define WV_BUF (256*72)
#define FIN_SMEM ((16*1032 + 2*WV_BUF)*2)
__global__ void __launch_bounds__(256) final_kernel(const float* __restrict__ bv,
                                                    const float* __restrict__ h0,
                                                    float* __restrict__ out,
                                                    int out_size) {
    extern __shared__ __nv_bfloat16 fs[];
    __nv_bfloat16* vsb  = fs;             // [16][1032]
    __nv_bfloat16* wv_s = fs + 16*1032;   // 2 x [256][72]
    int tid = threadIdx.x;
    int r0 = blockIdx.x * 16;

    // prologue: stage W_v chunk 0 behind phase-1
    #pragma unroll
    for (int j = 0; j < 8; j++) {
        int idx = j*256 + tid; int n = idx >> 3, u = idx & 7;
        cp16(s32(wv_s + n*72 + u*8), g_WvT + (size_t)n*1024 + u*8);
    }
    CP_COMMIT();

    // phase 1: normalize, convert bf16 (single accumulator now)
    #pragma unroll
    for (int ii = 0; ii < 16; ii++) {
        int idx = ii*256 + tid;
        int r = idx >> 8, c4 = idx & 255;
        int n = r0 + r;
        float4 a0 = *((const float4*)(g_acc + (size_t)n*1024) + c4);
        int b = c4 >> 6;
        float inv = 1.f / fmaxf(g_den[n*4 + b], 1e-12f);
        __nv_bfloat162 p0 = __float22bfloat162_rn(make_float2(a0.x*inv, a0.y*inv));
        __nv_bfloat162 p1 = __float22bfloat162_rn(make_float2(a0.z*inv, a0.w*inv));
        *(uint32_t*)(vsb + r*1032 + c4*4)     = *(uint32_t*)&p0;
        *(uint32_t*)(vsb + r*1032 + c4*4 + 2) = *(uint32_t*)&p1;
    }

    int w = tid >> 5, l = tid & 31, g = l >> 2, t2 = (l & 3)*2;
    int n0 = w * 32;
    uint32_t a_base = s32(vsb)  + (uint32_t)(((l & 15)*1032 + (l >> 4)*8) * 2);
    uint32_t b_base = s32(wv_s) + (uint32_t)((((l >> 4)*8 + (l & 7))*72 + ((l >> 3) & 1)*8) * 2);
    float acc[4][4];
    #pragma unroll
    for (int nt = 0; nt < 4; nt++) { acc[nt][0]=0.f; acc[nt][1]=0.f; acc[nt][2]=0.f; acc[nt][3]=0.f; }

    __syncthreads();   // vsb visible to all warps

    for (int kc = 0; kc < 16; kc++) {
        if (kc + 1 < 16) {
            __nv_bfloat16* wnx = wv_s + ((kc+1) & 1)*WV_BUF;
            #pragma unroll
            for (int j = 0; j < 8; j++) {
                int idx = j*256 + tid; int n = idx >> 3, u = idx & 7;
                cp16(s32(wnx + n*72 + u*8),
                     g_WvT + (size_t)n*1024 + (kc+1)*64 + u*8);
            }
            CP_COMMIT();
            CP_WAIT(1);
        } else {
            CP_WAIT(0);
        }
        __syncthreads();
        uint32_t boff = (uint32_t)(((kc & 1)*WV_BUF)*2);
        #pragma unroll
        for (int k16 = 0; k16 < 4; k16++) {
            uint32_t a[4];
            ldsm4(a, a_base + (uint32_t)((kc*64 + k16*16)*2));
            #pragma unroll
            for (int ntp = 0; ntp < 2; ntp++) {
                uint32_t bb[4];
                ldsm4(bb, b_base + boff + (uint32_t)(((n0 + ntp*16)*72 + k16*16)*2));
                mma16816(acc[ntp*2],   a, bb[0], bb[1]);
                mma16816(acc[ntp*2+1], a, bb[2], bb[3]);
            }
        }
        __syncthreads();   // guard buffer reuse two iterations later
    }

    #pragma unroll
    for (int nt = 0; nt < 4; nt++) {
        int oc = n0 + nt*8 + t2;
        float b0v = bv[oc], b1v = bv[oc+1];
        int m0 = r0 + g, m1 = m0 + 8;
        float u00 = acc[nt][0] + b0v, u01 = acc[nt][1] + b1v;
        float u10 = acc[nt][2] + b0v, u11 = acc[nt][3] + b1v;
        u00 = (u00 > 0.f) ? u00 : expm1f(u00);
        u01 = (u01 > 0.f) ? u01 : expm1f(u01);
        u10 = (u10 > 0.f) ? u10 : expm1f(u10);
        u11 = (u11 > 0.f) ? u11 : expm1f(u11);
        float2 hv0 = *(const float2*)(h0 + (size_t)m0*HH + oc);
        float2 hv1 = *(const float2*)(h0 + (size_t)m1*HH + oc);
        *(float2*)(out + (size_t)m0*HH + oc) = make_float2(u00 + hv0.x, u01 + hv0.y);
        *(float2*)(out + (size_t)m1*HH + oc) = make_float2(u10 + hv1.x, u11 + hv1.y);
    }
    if (blockIdx.x == 0 && tid == 0) {
        float klv = (float)(g_kl / ((double)NN * (double)NN));
        for (int i = NHID; i < out_size; i++) out[i] = klv;
    }
}

// ---------------- launch ----------------
extern "C" void kernel_launch(void* const* d_in, const int* in_sizes, int n_in,
                              void* d_out, int out_size) {
    const float* h     = (const float*)d_in[0];
    const float* gamma = (const float*)d_in[1];
    const float* beta  = (const float*)d_in[2];
    const float* Wk    = (const float*)d_in[3];
    const float* bk    = (const float*)d_in[4];
    const float* Wm    = (const float*)d_in[5];
    const float* bm    = (const float*)d_in[6];
    const float* Wl    = (const float*)d_in[7];
    const float* bl    = (const float*)d_in[8];
    const float* Wv    = (const float*)d_in[9];
    const float* bv    = (const float*)d_in[10];
    const float* diff  = (const float*)d_in[11];
    const float* eps   = (const float*)d_in[12];
    float* out = (float*)d_out;

    cudaFuncSetAttribute(attn_kernel, cudaFuncAttributeMaxDynamicSharedMemorySize,
                         ATTN_SMEM_BYTES);
    cudaFuncSetAttribute(proj_kernel, cudaFuncAttributeMaxDynamicSharedMemorySize,
                         PROJ_SMEM);
    cudaFuncSetAttribute(final_kernel, cudaFuncAttributeMaxDynamicSharedMemorySize,
                         FIN_SMEM);

    prep_kernel<<<NN + 192 + 256, 256>>>(h, gamma, beta, Wk, Wm, Wl, Wv);
    dim3 gp(NN/64, 3);
    proj_kernel<<<gp, 256, PROJ_SMEM>>>(bk, bm, bl);
    attn_kernel<<<(NN/32)*NSPLIT, 256, ATTN_SMEM_BYTES>>>(diff, eps);
    final_kernel<<<NN/16, 256, FIN_SMEM>>>(bv, h, out, out_size);
}

// round 7
// speedup vs baseline: 5.4763x; 1.0074x over previous
#include <cuda_runtime.h>
#include <cuda_bf16.h>
#include <stdint.h>
#include <math.h>

#define NN 3072
#define HH 256
#define HD 64
#define NHID (NN*HH)
#define NSPLIT 3
#define ZRANGE (NN/NSPLIT)   // 1024
#define ZTILE 32
#define NZI (ZRANGE/ZTILE)   // 32
#define SCALE 0.125f         // HD^-0.5

// ---------------- device scratch (static; no allocations) ----------------
__device__ __nv_bfloat16 g_hnB[NHID];                 // hn row-major bf16 (proj A)
__device__ __nv_bfloat16 g_hnT[HH*NN];                // hn transposed [h][n] bf16
__device__ __nv_bfloat16 g_kt[4*NN*HD];               // k  per head [b][n][y]
__device__ __nv_bfloat16 g_mut[4*NN*HD];              // mu per head
__device__ __nv_bfloat16 g_lst[4*NN*HD];              // ls per head
__device__ __nv_bfloat16 g_WT[3*HH*HH];               // W_{k,mu,ls}^T bf16 [o][k]
__device__ __nv_bfloat16 g_WvT[HH*4*HH];              // W_v^T bf16 [256 o][1024 k]
__device__ float g_acc[(size_t)NN*1024];              // agg accumulator [n][b*256+h]
__device__ float g_den[NN*4];                         // denominators [n][b]
__device__ double g_kl;

// ---------------- PTX helpers ----------------
__device__ __forceinline__ void mma16816(float d[4], const uint32_t a[4],
                                         uint32_t b0, uint32_t b1) {
    asm volatile(
        "mma.sync.aligned.m16n8k16.row.col.f32.bf16.bf16.f32 "
        "{%0,%1,%2,%3},{%4,%5,%6,%7},{%8,%9},{%0,%1,%2,%3};\n"
        : "+f"(d[0]), "+f"(d[1]), "+f"(d[2]), "+f"(d[3])
        : "r"(a[0]), "r"(a[1]), "r"(a[2]), "r"(a[3]), "r"(b0), "r"(b1));
}
__device__ __forceinline__ void ldsm4(uint32_t r[4], uint32_t saddr) {
    asm volatile("ldmatrix.sync.aligned.m8n8.x4.shared.b16 {%0,%1,%2,%3}, [%4];\n"
        : "=r"(r[0]), "=r"(r[1]), "=r"(r[2]), "=r"(r[3]) : "r"(saddr));
}
__device__ __forceinline__ void cp16(uint32_t saddr, const void* g) {
    asm volatile("cp.async.cg.shared.global [%0], [%1], 16;\n" :: "r"(saddr), "l"(g));
}
#define CP_COMMIT() asm volatile("cp.async.commit_group;\n" ::: "memory")
#define CP_WAIT(n)  asm volatile("cp.async.wait_group %0;\n" :: "n"(n) : "memory")
__device__ __forceinline__ uint32_t s32(const void* p) {
    return (uint32_t)__cvta_generic_to_shared(p);
}

// ---------------- prep: LayerNorm + weight transposes + accumulator zeroing ----------------
__global__ void __launch_bounds__(256) prep_kernel(const float* __restrict__ h,
                                                   const float* __restrict__ gamma,
                                                   const float* __restrict__ beta,
                                                   const float* __restrict__ Wk,
                                                   const float* __restrict__ Wm,
                                                   const float* __restrict__ Wl,
                                                   const float* __restrict__ Wv) {
    __shared__ float sh[32][33];
    int bx = blockIdx.x, t = threadIdx.x;
    if (bx < NN) {
        int n = bx;
        *(float4*)(g_acc + (size_t)n*1024 + t*4) = make_float4(0.f,0.f,0.f,0.f);
        if (t == 0) *(float4*)(g_den + n*4) = make_float4(0.f,0.f,0.f,0.f);
        float v = h[n*HH + t];
        float s = v, q = v*v;
        #pragma unroll
        for (int o = 16; o; o >>= 1) {
            s += __shfl_down_sync(0xffffffffu, s, o);
            q += __shfl_down_sync(0xffffffffu, q, o);
        }
        __shared__ float ss[8], qs[8];
        __shared__ float s_m, s_r;
        int lane = t & 31, w = t >> 5;
        if (lane == 0) { ss[w] = s; qs[w] = q; }
        __syncthreads();
        if (t == 0) {
            float S = 0.f, Q = 0.f;
            #pragma unroll
            for (int i = 0; i < 8; i++) { S += ss[i]; Q += qs[i]; }
            float m = S * (1.f/256.f);
            float var = Q * (1.f/256.f) - m*m;
            s_m = m; s_r = rsqrtf(var + 1e-5f);
        }
        __syncthreads();
        float hn = (v - s_m) * s_r * gamma[t] + beta[t];
        __nv_bfloat16 hb = __float2bfloat16(hn);
        g_hnB[(size_t)n*HH + t] = hb;
        g_hnT[(size_t)t*NN + n] = hb;
        if (n == 0 && t == 0) g_kl = 0.0;
    } else {
        int tb = bx - NN;
        const float* src; __nv_bfloat16* dst; int K, O, o0, k0;
        if (tb < 192) {
            int p = tb >> 6, tl = tb & 63;
            src = (p == 0) ? Wk : (p == 1) ? Wm : Wl;
            dst = g_WT + (size_t)p*HH*HH;
            K = HH; O = HH; o0 = (tl & 7)*32; k0 = (tl >> 3)*32;
        } else {
            int tl = tb - 192;
            src = Wv; dst = g_WvT;
            K = 4*HH; O = HH; o0 = (tl & 7)*32; k0 = (tl >> 3)*32;
        }
        int tx = t & 31, ty = t >> 5;
        #pragma unroll
        for (int j = 0; j < 32; j += 8)
            sh[ty+j][tx] = src[(size_t)(k0+ty+j)*O + o0+tx];
        __syncthreads();
        #pragma unroll
        for (int j = 0; j < 32; j += 8)
            dst[(size_t)(o0+ty+j)*K + k0+tx] = __float2bfloat16(sh[tx][ty+j]);
    }
}

// ---------------- 3 projections (bf16 HMMA) -> head-transposed bf16 ----------------
#define PROJ_SMEM ((64*264 + 256*72)*2)
__global__ void __launch_bounds__(256) proj_kernel(const float* __restrict__ bk,
                                                   const float* __restrict__ bm,
                                                   const float* __restrict__ bl) {
    extern __shared__ __nv_bfloat16 ps[];
    __nv_bfloat16* a_s = ps;            // [64][264]
    __nv_bfloat16* b_s = ps + 64*264;   // [256][72]
    int p = blockIdx.y;
    const __nv_bfloat16* WT = g_WT + (size_t)p*HH*HH;
    const float* bi = (p == 0) ? bk : (p == 1) ? bm : bl;
    __nv_bfloat16* dst = (p == 0) ? g_kt : (p == 1) ? g_mut : g_lst;
    int tid = threadIdx.x;
    int r0 = blockIdx.x * 64;

    #pragma unroll
    for (int j = 0; j < 8; j++) {
        int idx = j*256 + tid; int row = idx >> 5, u = idx & 31;
        *(uint4*)(a_s + row*264 + u*8) =
            *(const uint4*)(g_hnB + (size_t)(r0+row)*HH + u*8);
    }

    int w = tid >> 5, l = tid & 31, t2 = (l & 3)*2, g = l >> 2;
    int wm = w >> 1, wn = w & 1;
    uint32_t a_base = s32(a_s) + (uint32_t)(((wm*16 + (l & 15))*264 + (l >> 4)*8) * 2);
    uint32_t b_base = s32(b_s) + (uint32_t)((((l >> 4)*8 + (l & 7))*72 + ((l >> 3) & 1)*8) * 2);
    float acc[16][4];
    #pragma unroll
    for (int nt = 0; nt < 16; nt++) { acc[nt][0]=0.f; acc[nt][1]=0.f; acc[nt][2]=0.f; acc[nt][3]=0.f; }

    for (int kc = 0; kc < 4; kc++) {
        __syncthreads();
        #pragma unroll
        for (int j = 0; j < 8; j++) {
            int idx = j*256 + tid; int o = idx >> 3, u = idx & 7;
            *(uint4*)(b_s + o*72 + u*8) =
                *(const uint4*)(WT + (size_t)o*HH + kc*64 + u*8);
        }
        __syncthreads();
        #pragma unroll
        for (int k16 = 0; k16 < 4; k16++) {
            uint32_t a[4];
            ldsm4(a, a_base + (uint32_t)((kc*64 + k16*16)*2));
            #pragma unroll
            for (int ntp = 0; ntp < 8; ntp++) {
                uint32_t bb[4];
                ldsm4(bb, b_base + (uint32_t)(((wn*128 + ntp*16)*72 + k16*16)*2));
                mma16816(acc[ntp*2],   a, bb[0], bb[1]);
                mma16816(acc[ntp*2+1], a, bb[2], bb[3]);
            }
        }
    }

    #pragma unroll
    for (int nt = 0; nt < 16; nt++) {
        int oc = wn*128 + nt*8 + t2;
        float b0v = bi[oc], b1v = bi[oc+1];
        int m0 = r0 + wm*16 + g, m1 = m0 + 8;
        dst[((size_t)(oc & 3)*NN + m0)*HD + (oc >> 2)]         = __float2bfloat16(acc[nt][0] + b0v);
        dst[((size_t)((oc+1) & 3)*NN + m0)*HD + ((oc+1) >> 2)] = __float2bfloat16(acc[nt][1] + b1v);
        dst[((size_t)(oc & 3)*NN + m1)*HD + (oc >> 2)]         = __float2bfloat16(acc[nt][2] + b0v);
        dst[((size_t)((oc+1) & 3)*NN + m1)*HD + ((oc+1) >> 2)] = __float2bfloat16(acc[nt][3] + b1v);
    }
}

// ---------------- fused attention: 32-z tiles, everything double-buffered ----------------
#define K_S_ELEMS  (4*32*72)     // 9216
#define MU_BUF     (4*ZTILE*72)  // 9216 el per buffer
#define HN_STRIDE  40
#define HN_BUF     (256*HN_STRIDE)   // 10240 el
#define BF_ELEMS   (K_S_ELEMS + 2*MU_BUF + 2*MU_BUF + 2*HN_BUF)
#define EPS_STRIDE 132
#define DIF_STRIDE 36
#define EPS_BUF (32*EPS_STRIDE)  // 4224 f32
#define DIF_BUF (32*DIF_STRIDE)  // 1152 f32
#define ATTN_SMEM_BYTES (BF_ELEMS*2 + (2*EPS_BUF + 2*DIF_BUF)*4)

__global__ void __launch_bounds__(256, 1) attn_kernel(const float* __restrict__ diff,
                                                      const float* __restrict__ eps) {
    extern __shared__ __nv_bfloat16 smb[];
    __nv_bfloat16* k_s  = smb;                        // [4][32][72]
    __nv_bfloat16* mu_s = k_s + K_S_ELEMS;            // 2 x [4*32][72]
    __nv_bfloat16* ls_s = mu_s + 2*MU_BUF;            // 2 x [4*32][72]
    __nv_bfloat16* hn_s = ls_s + 2*MU_BUF;            // 2 x [256][40]
    float* eps_s = (float*)(smb + BF_ELEMS);          // 2 x [32][132]
    float* dif_s = eps_s + 2*EPS_BUF;                 // 2 x [32][36]
    __shared__ float red[8];

    const int tid = threadIdx.x;
    const int xt = blockIdx.x / NSPLIT, sp = blockIdx.x % NSPLIT;
    const int x0 = xt * 32, zbase = sp * ZRANGE;
    const int w = tid >> 5, l = tid & 31;
    const int b = w >> 1, xh = w & 1;
    const int g = l >> 2, t2 = (l & 3) * 2;

    // staging index decomposition (per thread, 256 threads)
    const int srow = tid >> 1, su = tid & 1;      // unused placeholder

    uint32_t mu_fbase = s32(mu_s) + (uint32_t)(((b*ZTILE + (l & 7))*72 + (l >> 3)*8) * 2);
    uint32_t ls_fbase = s32(ls_s) + (uint32_t)(((b*ZTILE + (l & 7))*72 + (l >> 3)*8) * 2);
    uint32_t hn_fbase = s32(hn_s) + (uint32_t)((((l >> 4)*8 + (l & 7))*HN_STRIDE + ((l >> 3) & 1)*8) * 2);

    // ---- staging lambda bodies (manually inlined twice: prologue + loop) ----
    // mu/ls: 128 rows x 8 u4 = 1024 -> 4/thread ; hn: 256 rows x 4 u4 = 1024 -> 4/thread
    // eps: 32 rows x 32 f4 = 1024 -> 4/thread ; dif: 32 x 8 f4 = 256 -> 1/thread

    // prologue: K + S0 + E0 in one group
    #pragma unroll
    for (int j = 0; j < 4; j++) {
        int idx = j*256 + tid; int row = idx >> 3, u = idx & 7;
        int br = row >> 5, xr = row & 31;
        cp16(s32(k_s + (br*32 + xr)*72 + u*8),
             g_kt + ((size_t)br*NN + x0 + xr)*HD + u*8);
    }
    {
        const int zb = zbase;
        #pragma unroll
        for (int j = 0; j < 4; j++) {
            int idx = j*256 + tid; int row = idx >> 3, u = idx & 7;
            int bb_ = row >> 5, z_ = row & 31;
            cp16(s32(mu_s + row*72 + u*8),
                 g_mut + ((size_t)bb_*NN + zb + z_)*HD + u*8);
            cp16(s32(ls_s + row*72 + u*8),
                 g_lst + ((size_t)bb_*NN + zb + z_)*HD + u*8);
        }
        #pragma unroll
        for (int j = 0; j < 4; j++) {
            int idx = j*256 + tid; int hr = idx >> 2, u = idx & 3;
            cp16(s32(hn_s + hr*HN_STRIDE + u*8),
                 g_hnT + (size_t)hr*NN + zb + u*8);
        }
        #pragma unroll
        for (int j = 0; j < 4; j++) {
            int idx = j*256 + tid; int x = idx >> 5, u = idx & 31;
            cp16(s32(eps_s + x*EPS_STRIDE + u*4),
                 eps + ((size_t)(x0+x)*NN + zb)*4 + u*4);
        }
        {
            int x = tid >> 3, u = tid & 7;
            cp16(s32(dif_s + x*DIF_STRIDE + u*4),
                 diff + (size_t)(x0+x)*NN + zb + u*4);
        }
    }
    CP_COMMIT();

    float acc[32][4];
    #pragma unroll
    for (int nt = 0; nt < 32; nt++) { acc[nt][0]=0.f; acc[nt][1]=0.f; acc[nt][2]=0.f; acc[nt][3]=0.f; }
    float den0 = 0.f, den1 = 0.f, klloc = 0.f;
    uint32_t kfr[4][4];

    const int xr_lo = x0 + xh*16 + g;

    for (int zi = 0; zi < NZI; ++zi) {
        __syncthreads();   // all warps done reading buffers from zi-1

        // ---- prefetch S+E for zi+1 into alternate buffer ----
        if (zi + 1 < NZI) {
            const int zb = zbase + (zi+1)*ZTILE;
            const int nb = (zi+1) & 1;
            __nv_bfloat16* mnx = mu_s + nb*MU_BUF;
            __nv_bfloat16* lnx = ls_s + nb*MU_BUF;
            __nv_bfloat16* hnx = hn_s + nb*HN_BUF;
            float* enx = eps_s + nb*EPS_BUF;
            float* dnx = dif_s + nb*DIF_BUF;
            #pragma unroll
            for (int j = 0; j < 4; j++) {
                int idx = j*256 + tid; int row = idx >> 3, u = idx & 7;
                int bb_ = row >> 5, z_ = row & 31;
                cp16(s32(mnx + row*72 + u*8),
                     g_mut + ((size_t)bb_*NN + zb + z_)*HD + u*8);
                cp16(s32(lnx + row*72 + u*8),
                     g_lst + ((size_t)bb_*NN + zb + z_)*HD + u*8);
            }
            #pragma unroll
            for (int j = 0; j < 4; j++) {
                int idx = j*256 + tid; int hr = idx >> 2, u = idx & 3;
                cp16(s32(hnx + hr*HN_STRIDE + u*8),
                     g_hnT + (size_t)hr*NN + zb + u*8);
            }
            #pragma unroll
            for (int j = 0; j < 4; j++) {
                int idx = j*256 + tid; int x = idx >> 5, u = idx & 31;
                cp16(s32(enx + x*EPS_STRIDE + u*4),
                     eps + ((size_t)(x0+x)*NN + zb)*4 + u*4);
            }
            {
                int x = tid >> 3, u = tid & 7;
                cp16(s32(dnx + x*DIF_STRIDE + u*4),
                     diff + (size_t)(x0+x)*NN + zb + u*4);
            }
            CP_COMMIT();
            CP_WAIT(1);    // group zi (committed one compute-phase ago) retired
        } else {
            CP_WAIT(0);
        }
        __syncthreads();

        const int cb = zi & 1;
        const float* ecur = eps_s + cb*EPS_BUF;
        const float* dcur = dif_s + cb*DIF_BUF;
        const uint32_t mu_base = mu_fbase + (uint32_t)(cb*MU_BUF*2);
        const uint32_t ls_base = ls_fbase + (uint32_t)(cb*MU_BUF*2);
        const uint32_t hn_base = hn_fbase + (uint32_t)(cb*HN_BUF*2);
        const int zb = zbase + zi*ZTILE;

        if (zi == 0) {
            #pragma unroll
            for (int kt = 0; kt < 4; kt++) {
                const __nv_bfloat16* base = k_s + (b*32 + xh*16)*72 + kt*16;
                kfr[kt][0] = *(const uint32_t*)(base + (size_t)g*72     + t2);
                kfr[kt][1] = *(const uint32_t*)(base + (size_t)(g+8)*72 + t2);
                kfr[kt][2] = *(const uint32_t*)(base + (size_t)g*72     + t2 + 8);
                kfr[kt][3] = *(const uint32_t*)(base + (size_t)(g+8)*72 + t2 + 8);
            }
        }

        #pragma unroll
        for (int zk = 0; zk < 2; zk++) {
            // ---- score MMAs ----
            float dmu[2][4], dls[2][4];
            #pragma unroll
            for (int t = 0; t < 2; t++) {
                dmu[t][0]=0.f; dmu[t][1]=0.f; dmu[t][2]=0.f; dmu[t][3]=0.f;
                dls[t][0]=0.f; dls[t][1]=0.f; dls[t][2]=0.f; dls[t][3]=0.f;
                uint32_t roff = (uint32_t)(((zk*16 + t*8)*72) * 2);
                uint32_t mb[4], lb[4];
                ldsm4(mb, mu_base + roff);
                mma16816(dmu[t], kfr[0], mb[0], mb[1]);
                mma16816(dmu[t], kfr[1], mb[2], mb[3]);
                ldsm4(mb, mu_base + roff + 64);
                mma16816(dmu[t], kfr[2], mb[0], mb[1]);
                mma16816(dmu[t], kfr[3], mb[2], mb[3]);
                ldsm4(lb, ls_base + roff);
                mma16816(dls[t], kfr[0], lb[0], lb[1]);
                mma16816(dls[t], kfr[1], lb[2], lb[3]);
                ldsm4(lb, ls_base + roff + 64);
                mma16816(dls[t], kfr[2], lb[0], lb[1]);
                mma16816(dls[t], kfr[3], lb[2], lb[3]);
            }

            // ---- elementwise ----
            uint32_t af[4];
            #pragma unroll
            for (int t = 0; t < 2; t++) {
                #pragma unroll
                for (int rr = 0; rr < 2; rr++) {
                    int lx = xh*16 + rr*8 + g;
                    int lz = zk*16 + t*8 + t2;
                    float2 dv = *(const float2*)(dcur + lx*DIF_STRIDE + lz);
                    const float* ep = ecur + lx*EPS_STRIDE + lz*4 + b;
                    float e0 = ep[0], e1 = ep[4];
                    float m0 = dmu[t][rr*2]   * SCALE;
                    float m1 = dmu[t][rr*2+1] * SCALE;
                    float s0 = dls[t][rr*2]   * SCALE;
                    float s1 = dls[t][rr*2+1] * SCALE;
                    float sg0 = __logf(1.f + __expf(s0));
                    float sg1 = __logf(1.f + __expf(s1));
                    float d0 = dv.x, d1 = dv.y;
                    float a0 = __expf(fmaf(sg0, e0, m0)) * d0;
                    float a1 = __expf(fmaf(sg1, e1, m1)) * d1;
                    float sn0 = (d0 > 0.f) ? 1.f : ((d0 < 0.f) ? -1.f : 0.f);
                    float sn1 = (d1 > 0.f) ? 1.f : ((d1 < 0.f) ? -1.f : 0.f);
                    klloc += sn0 * (0.5f*(sg0*sg0 + m0*m0) - 0.5f - __logf(sg0));
                    klloc += sn1 * (0.5f*(sg1*sg1 + m1*m1) - 0.5f - __logf(sg1));
                    if (rr == 0) den0 += a0 + a1; else den1 += a0 + a1;
                    __nv_bfloat162 p = __float22bfloat162_rn(make_float2(a0, a1));
                    af[t*2 + rr] = *(uint32_t*)&p;
                }
            }

            // ---- aggregation MMAs ----
            uint32_t zoff = (uint32_t)((zk*16)*2);
            #pragma unroll
            for (int ntp = 0; ntp < 16; ntp++) {
                uint32_t hb[4];
                ldsm4(hb, hn_base + (uint32_t)((ntp*16*HN_STRIDE)*2) + zoff);
                mma16816(acc[ntp*2],   af, hb[0], hb[1]);
                mma16816(acc[ntp*2+1], af, hb[2], hb[3]);
            }
        }
    }

    // ---- epilogue: atomic accumulation ----
    {
        float* outlo = g_acc + (size_t)xr_lo*1024 + b*256;
        float* outhi = outlo + (size_t)8*1024;
        #pragma unroll
        for (int nt = 0; nt < 32; nt++) {
            atomicAdd(outlo + nt*8 + t2,     acc[nt][0]);
            atomicAdd(outlo + nt*8 + t2 + 1, acc[nt][1]);
            atomicAdd(outhi + nt*8 + t2,     acc[nt][2]);
            atomicAdd(outhi + nt*8 + t2 + 1, acc[nt][3]);
        }
        den0 += __shfl_xor_sync(0xffffffffu, den0, 1);
        den0 += __shfl_xor_sync(0xffffffffu, den0, 2);
        den1 += __shfl_xor_sync(0xffffffffu, den1, 1);
        den1 += __shfl_xor_sync(0xffffffffu, den1, 2);
        if ((l & 3) == 0) {
            atomicAdd(g_den + xr_lo*4 + b,       den0);
            atomicAdd(g_den + (xr_lo + 8)*4 + b, den1);
        }
    }
    #pragma unroll
    for (int o = 16; o; o >>= 1) klloc += __shfl_down_sync(0xffffffffu, klloc, o);
    if (l == 0) red[w] = klloc;
    __syncthreads();
    if (tid == 0) {
        float s = 0.f;
        #pragma unroll
        for (int i = 0; i < 8; i++) s += red[i];
        atomicAdd(&g_kl, (double)s);
    }
}

// ---------------- normalize + fc_v (bf16 HMMA, cp.async double-buffer) ----------------
#define WV_BUF (256*72)
#define FIN_SMEM ((16*1032 + 2*WV_BUF)*2)
__global__ void __launch_bounds__(256) final_kernel(const float* __restrict__ bv,
                                                    const float* __restrict__ h0,
                                                    float* __restrict__ out,
                                                    int out_size) {
    extern __shared__ __nv_bfloat16 fs[];
    __nv_bfloat16* vsb  = fs;             // [16][1032]
    __nv_bfloat16* wv_s = fs + 16*1032;   // 2 x [256][72]
    int tid = threadIdx.x;
    int r0 = blockIdx.x * 16;

    #pragma unroll
    for (int j = 0; j < 8; j++) {
        int idx = j*256 + tid; int n = idx >> 3, u = idx & 7;
        cp16(s32(wv_s + n*72 + u*8), g_WvT + (size_t)n*1024 + u*8);
    }
    CP_COMMIT();

    #pragma unroll
    for (int ii = 0; ii < 16; ii++) {
        int idx = ii*256 + tid;
        int r = idx >> 8, c4 = idx & 255;
        int n = r0 + r;
        float4 a0 = *((const float4*)(g_acc + (size_t)n*1024) + c4);
        int b = c4 >> 6;
        float inv = 1.f / fmaxf(g_den[n*4 + b], 1e-12f);
        __nv_bfloat162 p0 = __float22bfloat162_rn(make_float2(a0.x*inv, a0.y*inv));
        __nv_bfloat162 p1 = __float22bfloat162_rn(make_float2(a0.z*inv, a0.w*inv));
        *(uint32_t*)(vsb + r*1032 + c4*4)     = *(uint32_t*)&p0;
        *(uint32_t*)(vsb + r*1032 + c4*4 + 2) = *(uint32_t*)&p1;
    }

    int w = tid >> 5, l = tid & 31, g = l >> 2, t2 = (l & 3)*2;
    int n0 = w * 32;
    uint32_t a_base = s32(vsb)  + (uint32_t)(((l & 15)*1032 + (l >> 4)*8) * 2);
    uint32_t b_base = s32(wv_s) + (uint32_t)((((l >> 4)*8 + (l & 7))*72 + ((l >> 3) & 1)*8) * 2);
    float acc[4][4];
    #pragma unroll
    for (int nt = 0; nt < 4; nt++) { acc[nt][0]=0.f; acc[nt][1]=0.f; acc[nt][2]=0.f; acc[nt][3]=0.f; }

    __syncthreads();

    for (int kc = 0; kc < 16; kc++) {
        if (kc + 1 < 16) {
            __nv_bfloat16* wnx = wv_s + ((kc+1) & 1)*WV_BUF;
            #pragma unroll
            for (int j = 0; j < 8; j++) {
                int idx = j*256 + tid; int n = idx >> 3, u = idx & 7;
                cp16(s32(wnx + n*72 + u*8),
                     g_WvT + (size_t)n*1024 + (kc+1)*64 + u*8);
            }
            CP_COMMIT();
            CP_WAIT(1);
        } else {
            CP_WAIT(0);
        }
        __syncthreads();
        uint32_t boff = (uint32_t)(((kc & 1)*WV_BUF)*2);
        #pragma unroll
        for (int k16 = 0; k16 < 4; k16++) {
            uint32_t a[4];
            ldsm4(a, a_base + (uint32_t)((kc*64 + k16*16)*2));
            #pragma unroll
            for (int ntp = 0; ntp < 2; ntp++) {
                uint32_t bb[4];
                ldsm4(bb, b_base + boff + (uint32_t)(((n0 + ntp*16)*72 + k16*16)*2));
                mma16816(acc[ntp*2],   a, bb[0], bb[1]);
                mma16816(acc[ntp*2+1], a, bb[2], bb[3]);
            }
        }
        __syncthreads();
    }

    #pragma unroll
    for (int nt = 0; nt < 4; nt++) {
        int oc = n0 + nt*8 + t2;
        float b0v = bv[oc], b1v = bv[oc+1];
        int m0 = r0 + g, m1 = m0 + 8;
        float u00 = acc[nt][0] + b0v, u01 = acc[nt][1] + b1v;
        float u10 = acc[nt][2] + b0v, u11 = acc[nt][3] + b1v;
        u00 = (u00 > 0.f) ? u00 : expm1f(u00);
        u01 = (u01 > 0.f) ? u01 : expm1f(u01);
        u10 = (u10 > 0.f) ? u10 : expm1f(u10);
        u11 = (u11 > 0.f) ? u11 : expm1f(u11);
        float2 hv0 = *(const float2*)(h0 + (size_t)m0*HH + oc);
        float2 hv1 = *(const float2*)(h0 + (size_t)m1*HH + oc);
        *(float2*)(out + (size_t)m0*HH + oc) = make_float2(u00 + hv0.x, u01 + hv0.y);
        *(float2*)(out + (size_t)m1*HH + oc) = make_float2(u10 + hv1.x, u11 + hv1.y);
    }
    if (blockIdx.x == 0 && tid == 0) {
        float klv = (float)(g_kl / ((double)NN * (double)NN));
        for (int i = NHID; i < out_size; i++) out[i] = klv;
    }
}

// ---------------- launch ----------------
extern "C" void kernel_launch(void* const* d_in, const int* in_sizes, int n_in,
                              void* d_out, int out_size) {
    const float* h     = (const float*)d_in[0];
    const float* gamma = (const float*)d_in[1];
    const float* beta  = (const float*)d_in[2];
    const float* Wk    = (const float*)d_in[3];
    const float* bk    = (const float*)d_in[4];
    const float* Wm    = (const float*)d_in[5];
    const float* bm    = (const float*)d_in[6];
    const float* Wl    = (const float*)d_in[7];
    const float* bl    = (const float*)d_in[8];
    const float* Wv    = (const float*)d_in[9];
    const float* bv    = (const float*)d_in[10];
    const float* diff  = (const float*)d_in[11];
    const float* eps   = (const float*)d_in[12];
    float* out = (float*)d_out;

    cudaFuncSetAttribute(attn_kernel, cudaFuncAttributeMaxDynamicSharedMemorySize,
                         ATTN_SMEM_BYTES);
    cudaFuncSetAttribute(proj_kernel, cudaFuncAttributeMaxDynamicSharedMemorySize,
                         PROJ_SMEM);
    cudaFuncSetAttribute(final_kernel, cudaFuncAttributeMaxDynamicSharedMemorySize,
                         FIN_SMEM);

    prep_kernel<<<NN + 192 + 256, 256>>>(h, gamma, beta, Wk, Wm, Wl, Wv);
    dim3 gp(NN/64, 3);
    proj_kernel<<<gp, 256, PROJ_SMEM>>>(bk, bm, bl);
    attn_kernel<<<(NN/32)*NSPLIT, 256, ATTN_SMEM_BYTES>>>(diff, eps);
    final_kernel<<<NN/16, 256, FIN_SMEM>>>(bv, h, out, out_size);
}